// round 2
// baseline (speedup 1.0000x reference)
#include <cuda_runtime.h>
#include <math.h>

// ---------------------------------------------------------------------------
// Shapes fixed by dataset.
// ---------------------------------------------------------------------------
#define TM 128          // tokens per CTA
#define THREADS 512
#define D_IN 64
#define H1N 128
#define H2N 64
#define H3N 16

// smem pitches (floats) — even (8B pairs), not multiples of 32
#define H1P 130
#define H2P 66
#define H3P 18

// smem float offsets (all 16B-aligned)
#define OFF_WP1 0                        // 8192  (k-pair interleaved, as ull[4096])
#define OFF_WP2 (OFF_WP1 + 8192)         // 8192
#define OFF_WP3 (OFF_WP2 + 8192)         // 1024
#define OFF_B1  (OFF_WP3 + 1024)         // 128
#define OFF_B2  (OFF_B1 + 128)           // 64
#define OFF_B3  (OFF_B2 + 64)            // 16
#define OFF_W4  (OFF_B3 + 16)            // 16 (natural order = k-pairs)
#define OFF_B4  (OFF_W4 + 16)            // 4
#define OFF_X   (OFF_B4 + 4)             // 128*64 = 8192 (row-major, pitch 64)
#define OFF_H1  (OFF_X + 8192)           // 128*130 = 16640
#define OFF_H2  (OFF_H1 + 128*H1P)       // 128*66 = 8448
#define OFF_H3  (OFF_H2 + 128*H2P)       // 128*18 = 2304
#define SMEM_FLOATS (OFF_H3 + 128*H3P)
#define SMEM_BYTES (SMEM_FLOATS * 4)     // 212,880 B < 227 KB

__device__ float g_logits[1 << 20];

typedef unsigned long long ull;

__device__ __forceinline__ ull pk(float lo, float hi) {
    ull r;
    asm("mov.b64 %0, {%1, %2};" : "=l"(r) : "f"(lo), "f"(hi));
    return r;
}
__device__ __forceinline__ void unpk(ull v, float& lo, float& hi) {
    asm("mov.b64 {%0, %1}, %2;" : "=f"(lo), "=f"(hi) : "l"(v));
}
__device__ __forceinline__ ull fma2(ull a, ull b, ull c) {
    ull d;
    asm("fma.rn.f32x2 %0, %1, %2, %3;" : "=l"(d) : "l"(a), "l"(b), "l"(c));
    return d;
}

// accurate fast tanh: MUFU.EX2 + MUFU.RCP path, err ~1e-6
__device__ __forceinline__ float tanh_fast(float x) {
    float e = __expf(2.0f * x);
    return 1.0f - __fdividef(2.0f, e + 1.0f);
}
__device__ __forceinline__ float tanh_merge(ull v) {
    float lo, hi; unpk(v, lo, hi);
    return tanh_fast(lo + hi);
}

// ---------------------------------------------------------------------------
// Fused 4-layer MLP -> logits. One CTA = 128 tokens, 512 threads.
// Weights pre-interleaved by k-pairs so every FFMA2 consumes natural LDS.64
// pairs on both operands (no broadcast MOVs, no duplicated storage).
// ---------------------------------------------------------------------------
__global__ void __launch_bounds__(THREADS, 1)
mlp_kernel(const float* __restrict__ x,
           const float* __restrict__ W1, const float* __restrict__ b1,
           const float* __restrict__ W2, const float* __restrict__ b2,
           const float* __restrict__ W3, const float* __restrict__ b3,
           const float* __restrict__ W4, const float* __restrict__ b4) {
    extern __shared__ float sm[];
    ull*   sWp1 = (ull*)(sm + OFF_WP1);
    ull*   sWp2 = (ull*)(sm + OFF_WP2);
    ull*   sWp3 = (ull*)(sm + OFF_WP3);
    float* sB1  = sm + OFF_B1;
    float* sB2  = sm + OFF_B2;
    float* sB3  = sm + OFF_B3;
    float* sW4  = sm + OFF_W4;
    float* sB4  = sm + OFF_B4;
    float* sX   = sm + OFF_X;
    float* sH1  = sm + OFF_H1;
    float* sH2  = sm + OFF_H2;
    float* sH3  = sm + OFF_H3;
    float* sWp1f = sm + OFF_WP1;
    float* sWp2f = sm + OFF_WP2;
    float* sWp3f = sm + OFF_WP3;

    const int tid = threadIdx.x;
    const long long base = (long long)blockIdx.x * TM;

    // ---- stage weights, interleaving k-pairs: Wp[k/2][n] = (W[k][n], W[k+1][n]) ----
    {
#pragma unroll
        for (int it = 0; it < 16; it++) {
            int i = tid + it * THREADS;          // i < 8192
            int k = i >> 7, n = i & 127;
            sWp1f[(((k >> 1) * H1N + n) << 1) + (k & 1)] = W1[i];
        }
#pragma unroll
        for (int it = 0; it < 16; it++) {
            int i = tid + it * THREADS;
            int k = i >> 6, n = i & 63;
            sWp2f[(((k >> 1) * H2N + n) << 1) + (k & 1)] = W2[i];
        }
#pragma unroll
        for (int it = 0; it < 2; it++) {
            int i = tid + it * THREADS;          // i < 1024
            int k = i >> 4, n = i & 15;
            sWp3f[(((k >> 1) * H3N + n) << 1) + (k & 1)] = W3[i];
        }
        if (tid < 128) sB1[tid] = b1[tid];
        if (tid < 64)  sB2[tid] = b2[tid];
        if (tid < 16)  { sB3[tid] = b3[tid]; sW4[tid] = W4[tid]; }
        if (tid == 0)  sB4[0] = b4[0];
    }
    // ---- stage X tile (row-major, pitch 64 == contiguous) ----
    {
        const float4* gx = (const float4*)(x + base * D_IN);
        float4* dx = (float4*)sX;
#pragma unroll
        for (int it = 0; it < 4; it++) dx[tid + it * THREADS] = gx[tid + it * THREADS];
    }
    __syncthreads();

    const int tx = tid & 15;    // n-lane (columns strided by 16: conflict-free)
    const int ty = tid >> 4;    // 0..31
    const int m0 = ty * 4;      // 4 rows per thread

    // ======================= Layer 1: [128x64] @ [64x128] ===================
    {
        ull acc[4][8];
#pragma unroll
        for (int j = 0; j < 8; j++) {
            ull b = pk(sB1[tx + 16 * j], 0.0f);
#pragma unroll
            for (int i = 0; i < 4; i++) acc[i][j] = b;
        }
#pragma unroll 2
        for (int k2 = 0; k2 < D_IN / 2; k2++) {
            ull xv[4], wv[8];
#pragma unroll
            for (int i = 0; i < 4; i++) xv[i] = *(const ull*)&sX[(m0 + i) * D_IN + 2 * k2];
#pragma unroll
            for (int j = 0; j < 8; j++) wv[j] = sWp1[k2 * H1N + tx + 16 * j];
#pragma unroll
            for (int i = 0; i < 4; i++)
#pragma unroll
                for (int j = 0; j < 8; j++) acc[i][j] = fma2(xv[i], wv[j], acc[i][j]);
        }
#pragma unroll
        for (int i = 0; i < 4; i++)
#pragma unroll
            for (int j = 0; j < 8; j++)
                sH1[(m0 + i) * H1P + tx + 16 * j] = tanh_merge(acc[i][j]);
    }
    __syncthreads();

    // ======================= Layer 2: [128x128] @ [128x64] ==================
    {
        ull acc[4][4];
#pragma unroll
        for (int j = 0; j < 4; j++) {
            ull b = pk(sB2[tx + 16 * j], 0.0f);
#pragma unroll
            for (int i = 0; i < 4; i++) acc[i][j] = b;
        }
#pragma unroll 2
        for (int k2 = 0; k2 < H1N / 2; k2++) {
            ull xv[4], wv[4];
#pragma unroll
            for (int i = 0; i < 4; i++) xv[i] = *(const ull*)&sH1[(m0 + i) * H1P + 2 * k2];
#pragma unroll
            for (int j = 0; j < 4; j++) wv[j] = sWp2[k2 * H2N + tx + 16 * j];
#pragma unroll
            for (int i = 0; i < 4; i++)
#pragma unroll
                for (int j = 0; j < 4; j++) acc[i][j] = fma2(xv[i], wv[j], acc[i][j]);
        }
#pragma unroll
        for (int i = 0; i < 4; i++)
#pragma unroll
            for (int j = 0; j < 4; j++)
                sH2[(m0 + i) * H2P + tx + 16 * j] = tanh_merge(acc[i][j]);
    }
    __syncthreads();

    // ======================= Layer 3: [128x64] @ [64x16] ====================
    {
        ull acc[4];
        {
            ull b = pk(sB3[tx], 0.0f);
#pragma unroll
            for (int i = 0; i < 4; i++) acc[i] = b;
        }
#pragma unroll 4
        for (int k2 = 0; k2 < H2N / 2; k2++) {
            ull wv = sWp3[k2 * H3N + tx];
#pragma unroll
            for (int i = 0; i < 4; i++) {
                ull xv = *(const ull*)&sH2[(m0 + i) * H2P + 2 * k2];
                acc[i] = fma2(xv, wv, acc[i]);
            }
        }
#pragma unroll
        for (int i = 0; i < 4; i++)
            sH3[(m0 + i) * H3P + tx] = tanh_merge(acc[i]);
    }
    __syncthreads();

    // ======================= Layer 4: [128x16] @ [16x1] =====================
    if (tid < TM) {
        ull acc = pk(sB4[0], 0.0f);
#pragma unroll
        for (int j = 0; j < 8; j++) {
            ull xv = *(const ull*)&sH3[tid * H3P + 2 * j];
            ull wv = *(const ull*)&sW4[2 * j];   // natural order == k-pairs
            acc = fma2(xv, wv, acc);
        }
        float lo, hi; unpk(acc, lo, hi);
        g_logits[base + tid] = lo + hi;
    }
}

// ---------------------------------------------------------------------------
// Per-segment softmax (global-max subtraction cancels; per-segment max is
// mathematically identical). One CTA per segment.
// ---------------------------------------------------------------------------
#define SOFT_THREADS 512

__device__ __forceinline__ float warpRedMax(float v) {
#pragma unroll
    for (int o = 16; o > 0; o >>= 1) v = fmaxf(v, __shfl_xor_sync(0xffffffffu, v, o));
    return v;
}
__device__ __forceinline__ float warpRedSum(float v) {
#pragma unroll
    for (int o = 16; o > 0; o >>= 1) v += __shfl_xor_sync(0xffffffffu, v, o);
    return v;
}
__device__ __forceinline__ int warpRedSumI(int v) {
#pragma unroll
    for (int o = 16; o > 0; o >>= 1) v += __shfl_xor_sync(0xffffffffu, v, o);
    return v;
}

__global__ void __launch_bounds__(SOFT_THREADS)
softmax_seg_kernel(const int* __restrict__ sizes, float* __restrict__ out) {
    __shared__ float shf[16];
    __shared__ int shi[16];
    __shared__ float bcastf;
    __shared__ int bcasti;

    const int b = blockIdx.x;
    const int tid = threadIdx.x;
    const int wid = tid >> 5, lid = tid & 31;
    const int nwarp = SOFT_THREADS / 32;

    int part = 0;
    for (int i = tid; i < b; i += SOFT_THREADS) part += sizes[i];
    part = warpRedSumI(part);
    if (lid == 0) shi[wid] = part;
    __syncthreads();
    if (wid == 0) {
        int v = (lid < nwarp) ? shi[lid] : 0;
        v = warpRedSumI(v);
        if (lid == 0) bcasti = v;
    }
    __syncthreads();
    const int off = bcasti;
    const int len = sizes[b];

    float mx = -3.402823466e38f;
    for (int i = tid; i < len; i += SOFT_THREADS) mx = fmaxf(mx, g_logits[off + i]);
    mx = warpRedMax(mx);
    if (lid == 0) shf[wid] = mx;
    __syncthreads();
    if (wid == 0) {
        float v = (lid < nwarp) ? shf[lid] : -3.402823466e38f;
        v = warpRedMax(v);
        if (lid == 0) bcastf = v;
    }
    __syncthreads();
    mx = bcastf;

    float s = 0.0f;
    for (int i = tid; i < len; i += SOFT_THREADS) {
        float e = __expf(g_logits[off + i] - mx);
        out[off + i] = e;
        s += e;
    }
    s = warpRedSum(s);
    __syncthreads();
    if (lid == 0) shf[wid] = s;
    __syncthreads();
    if (wid == 0) {
        float v = (lid < nwarp) ? shf[lid] : 0.0f;
        v = warpRedSum(v);
        if (lid == 0) bcastf = v;
    }
    __syncthreads();
    const float inv = 1.0f / bcastf;

    for (int i = tid; i < len; i += SOFT_THREADS) out[off + i] *= inv;
}

__global__ void tail_sizes_kernel(const int* __restrict__ sizes, float* __restrict__ out,
                                  int n, int basepos) {
    int i = blockIdx.x * blockDim.x + threadIdx.x;
    if (i < n) out[basepos + i] = (float)sizes[i];
}

// ---------------------------------------------------------------------------
extern "C" void kernel_launch(void* const* d_in, const int* in_sizes, int n_in,
                              void* d_out, int out_size) {
    const float* x   = (const float*)d_in[0];
    const int* sizes = (const int*)d_in[1];
    const float* W1  = (const float*)d_in[2];
    const float* b1  = (const float*)d_in[3];
    const float* W2  = (const float*)d_in[4];
    const float* b2  = (const float*)d_in[5];
    const float* W3  = (const float*)d_in[6];
    const float* b3  = (const float*)d_in[7];
    const float* W4  = (const float*)d_in[8];
    const float* b4  = (const float*)d_in[9];
    float* out = (float*)d_out;

    const int total = in_sizes[0] / D_IN;
    const int B     = in_sizes[1];

    cudaFuncSetAttribute(mlp_kernel, cudaFuncAttributeMaxDynamicSharedMemorySize, SMEM_BYTES);

    mlp_kernel<<<total / TM, THREADS, SMEM_BYTES>>>(x, W1, b1, W2, b2, W3, b3, W4, b4);
    softmax_seg_kernel<<<B, SOFT_THREADS>>>(sizes, out);

    if (out_size > total) {
        int n = out_size - total;
        tail_sizes_kernel<<<(n + 255) / 256, 256>>>(sizes, out, n, total);
    }
}

// round 4
// speedup vs baseline: 2.4267x; 2.4267x over previous
#include <cuda_runtime.h>
#include <cuda_bf16.h>
#include <stdint.h>

#define THREADS 256
#define TM 128
#define D_IN 64

// ---- smem byte offsets ----
#define XB    0          // X tile: 128x64 f32 = 32768
#define W1H_B 32768      // 32 k2-rows x 136 u32 pitch = 17408
#define W1L_B 50176
#define W2H_B 67584      // 64 x 72 u32 = 18432
#define W2L_B 86016
#define W3H_B 104448     // 32 x 24 u32 = 3072
#define W3L_B 107520
#define B1_B  110592
#define B2_B  111104
#define B3_B  111360
#define W4_B  111424
#define B4_B  111488
#define SMEM_BYTES 111616

#define P1 136   // u32 pitch (128+8): pitch%32==8 -> conflict-free B frags
#define P2 72    // 64+8
#define P3 24    // 16+8: 24*k mod 32 cycles {0,24,16,8} -> conflict-free

__device__ float g_logits[1 << 20];

// ---- helpers ----
__device__ __forceinline__ void mma16816(float* c, const uint32_t* a, uint32_t b0, uint32_t b1) {
    asm volatile(
        "mma.sync.aligned.m16n8k16.row.col.f32.bf16.bf16.f32 "
        "{%0,%1,%2,%3}, {%4,%5,%6,%7}, {%8,%9}, {%0,%1,%2,%3};"
        : "+f"(c[0]), "+f"(c[1]), "+f"(c[2]), "+f"(c[3])
        : "r"(a[0]), "r"(a[1]), "r"(a[2]), "r"(a[3]), "r"(b0), "r"(b1));
}

// pack 2 floats to bf16x2 (lo = first) and return residuals
__device__ __forceinline__ uint32_t pack_hi(float a, float b, float& ra, float& rb) {
    __nv_bfloat162 h = __float22bfloat162_rn(make_float2(a, b));
    float2 hf = __bfloat1622float2(h);
    ra = a - hf.x; rb = b - hf.y;
    return *(uint32_t*)&h;
}
__device__ __forceinline__ uint32_t pack2(float a, float b) {
    __nv_bfloat162 h = __float22bfloat162_rn(make_float2(a, b));
    return *(uint32_t*)&h;
}

// accurate fast tanh: 2 MUFU, err ~1e-6
__device__ __forceinline__ float tanh_fast(float x) {
    float e = __expf(2.0f * x);
    return 1.0f - __fdividef(2.0f, e + 1.0f);
}

// ---------------------------------------------------------------------------
// Fused MLP: 1 CTA = 128 tokens, 8 warps x 16 tokens, all activations in regs.
// ---------------------------------------------------------------------------
__global__ void __launch_bounds__(THREADS, 1)
mlp_hmma_kernel(const float* __restrict__ x,
                const float* __restrict__ W1, const float* __restrict__ b1,
                const float* __restrict__ W2, const float* __restrict__ b2,
                const float* __restrict__ W3, const float* __restrict__ b3,
                const float* __restrict__ W4, const float* __restrict__ b4) {
    extern __shared__ char smem[];
    float* sX  = (float*)(smem + XB);
    __nv_bfloat16* s1h = (__nv_bfloat16*)(smem + W1H_B);
    __nv_bfloat16* s1l = (__nv_bfloat16*)(smem + W1L_B);
    __nv_bfloat16* s2h = (__nv_bfloat16*)(smem + W2H_B);
    __nv_bfloat16* s2l = (__nv_bfloat16*)(smem + W2L_B);
    __nv_bfloat16* s3h = (__nv_bfloat16*)(smem + W3H_B);
    __nv_bfloat16* s3l = (__nv_bfloat16*)(smem + W3L_B);
    const uint32_t* u1h = (const uint32_t*)(smem + W1H_B);
    const uint32_t* u1l = (const uint32_t*)(smem + W1L_B);
    const uint32_t* u2h = (const uint32_t*)(smem + W2H_B);
    const uint32_t* u2l = (const uint32_t*)(smem + W2L_B);
    const uint32_t* u3h = (const uint32_t*)(smem + W3H_B);
    const uint32_t* u3l = (const uint32_t*)(smem + W3L_B);
    float* sB1 = (float*)(smem + B1_B);
    float* sB2 = (float*)(smem + B2_B);
    float* sB3 = (float*)(smem + B3_B);
    float* sW4 = (float*)(smem + W4_B);
    float* sB4 = (float*)(smem + B4_B);

    const int tid = threadIdx.x;
    const long long base = (long long)blockIdx.x * TM;

    // ---- stage weights -> k-pair bf16x2 hi/lo layout ----
#pragma unroll
    for (int it = 0; it < 32; it++) {             // W1: 64k x 128n
        int i = tid + it * THREADS;
        int k = i >> 7, n = i & 127;
        float w = W1[i];
        __nv_bfloat16 h = __float2bfloat16_rn(w);
        __nv_bfloat16 l = __float2bfloat16_rn(w - __bfloat162float(h));
        int idx = (((k >> 1) * P1 + n) << 1) + (k & 1);
        s1h[idx] = h; s1l[idx] = l;
    }
#pragma unroll
    for (int it = 0; it < 32; it++) {             // W2: 128k x 64n
        int i = tid + it * THREADS;
        int k = i >> 6, n = i & 63;
        float w = W2[i];
        __nv_bfloat16 h = __float2bfloat16_rn(w);
        __nv_bfloat16 l = __float2bfloat16_rn(w - __bfloat162float(h));
        int idx = (((k >> 1) * P2 + n) << 1) + (k & 1);
        s2h[idx] = h; s2l[idx] = l;
    }
#pragma unroll
    for (int it = 0; it < 4; it++) {              // W3: 64k x 16n
        int i = tid + it * THREADS;
        int k = i >> 4, n = i & 15;
        float w = W3[i];
        __nv_bfloat16 h = __float2bfloat16_rn(w);
        __nv_bfloat16 l = __float2bfloat16_rn(w - __bfloat162float(h));
        int idx = (((k >> 1) * P3 + n) << 1) + (k & 1);
        s3h[idx] = h; s3l[idx] = l;
    }
    // ---- stage X (coalesced float4) ----
    {
        const float4* gx = (const float4*)(x + base * D_IN);
        float4* dx = (float4*)sX;
#pragma unroll
        for (int it = 0; it < 8; it++) dx[tid + it * THREADS] = gx[tid + it * THREADS];
    }
    if (tid < 128) sB1[tid] = b1[tid];
    if (tid < 64)  sB2[tid] = b2[tid];
    if (tid < 16)  { sB3[tid] = b3[tid]; sW4[tid] = W4[tid]; }
    if (tid == 0)  sB4[0] = b4[0];
    __syncthreads();

    // -------- per-warp, fully independent from here --------
    const int wid = tid >> 5, lid = tid & 31;
    const int m0 = wid * 16;
    const int g  = lid >> 2;        // group row 0..7
    const int q  = lid & 3;         // quad col 0..3

    // ---- A1 fragments from X ----
    uint32_t a1h[4][4], a1l[4][4];
#pragma unroll
    for (int kk = 0; kk < 4; kk++) {
        int c0 = q * 2 + 16 * kk;
        float2 p00 = *(float2*)&sX[(m0 + g) * 64 + c0];
        float2 p10 = *(float2*)&sX[(m0 + g + 8) * 64 + c0];
        float2 p01 = *(float2*)&sX[(m0 + g) * 64 + c0 + 8];
        float2 p11 = *(float2*)&sX[(m0 + g + 8) * 64 + c0 + 8];
        float r0, r1;
        a1h[kk][0] = pack_hi(p00.x, p00.y, r0, r1); a1l[kk][0] = pack2(r0, r1);
        a1h[kk][1] = pack_hi(p10.x, p10.y, r0, r1); a1l[kk][1] = pack2(r0, r1);
        a1h[kk][2] = pack_hi(p01.x, p01.y, r0, r1); a1l[kk][2] = pack2(r0, r1);
        a1h[kk][3] = pack_hi(p11.x, p11.y, r0, r1); a1l[kk][3] = pack2(r0, r1);
    }

    // ======== Layer 1: [16x64] @ [64x128] ========
    float acc1[16][4];
#pragma unroll
    for (int j = 0; j < 16; j++) { acc1[j][0] = acc1[j][1] = acc1[j][2] = acc1[j][3] = 0.0f; }
#pragma unroll
    for (int kk = 0; kk < 4; kk++) {
#pragma unroll
        for (int j = 0; j < 16; j++) {
            int r0 = (8 * kk + q) * P1 + 8 * j + g;
            int r1 = (8 * kk + 4 + q) * P1 + 8 * j + g;
            uint32_t bh0 = u1h[r0], bh1 = u1h[r1];
            uint32_t bl0 = u1l[r0], bl1 = u1l[r1];
            mma16816(acc1[j], a1h[kk], bh0, bh1);
            mma16816(acc1[j], a1l[kk], bh0, bh1);
            mma16816(acc1[j], a1h[kk], bl0, bl1);
        }
    }
    // epilogue 1 -> A2 fragments
    uint32_t a2h[8][4], a2l[8][4];
#pragma unroll
    for (int j = 0; j < 16; j++) {
        float2 bp = *(float2*)&sB1[8 * j + 2 * q];
        float t0 = tanh_fast(acc1[j][0] + bp.x);
        float t1 = tanh_fast(acc1[j][1] + bp.y);
        float t2 = tanh_fast(acc1[j][2] + bp.x);
        float t3 = tanh_fast(acc1[j][3] + bp.y);
        int kk = j >> 1, o = (j & 1) * 2;
        float r0, r1;
        a2h[kk][o]     = pack_hi(t0, t1, r0, r1); a2l[kk][o]     = pack2(r0, r1);
        a2h[kk][o + 1] = pack_hi(t2, t3, r0, r1); a2l[kk][o + 1] = pack2(r0, r1);
    }

    // ======== Layer 2: [16x128] @ [128x64] ========
    float acc2[8][4];
#pragma unroll
    for (int j = 0; j < 8; j++) { acc2[j][0] = acc2[j][1] = acc2[j][2] = acc2[j][3] = 0.0f; }
#pragma unroll
    for (int kk = 0; kk < 8; kk++) {
#pragma unroll
        for (int j = 0; j < 8; j++) {
            int r0 = (8 * kk + q) * P2 + 8 * j + g;
            int r1 = (8 * kk + 4 + q) * P2 + 8 * j + g;
            uint32_t bh0 = u2h[r0], bh1 = u2h[r1];
            uint32_t bl0 = u2l[r0], bl1 = u2l[r1];
            mma16816(acc2[j], a2h[kk], bh0, bh1);
            mma16816(acc2[j], a2l[kk], bh0, bh1);
            mma16816(acc2[j], a2h[kk], bl0, bl1);
        }
    }
    // epilogue 2 -> A3 fragments
    uint32_t a3h[4][4], a3l[4][4];
#pragma unroll
    for (int j = 0; j < 8; j++) {
        float2 bp = *(float2*)&sB2[8 * j + 2 * q];
        float t0 = tanh_fast(acc2[j][0] + bp.x);
        float t1 = tanh_fast(acc2[j][1] + bp.y);
        float t2 = tanh_fast(acc2[j][2] + bp.x);
        float t3 = tanh_fast(acc2[j][3] + bp.y);
        int kk = j >> 1, o = (j & 1) * 2;
        float r0, r1;
        a3h[kk][o]     = pack_hi(t0, t1, r0, r1); a3l[kk][o]     = pack2(r0, r1);
        a3h[kk][o + 1] = pack_hi(t2, t3, r0, r1); a3l[kk][o + 1] = pack2(r0, r1);
    }

    // ======== Layer 3: [16x64] @ [64x16] ========
    float acc3[2][4];
#pragma unroll
    for (int j = 0; j < 2; j++) { acc3[j][0] = acc3[j][1] = acc3[j][2] = acc3[j][3] = 0.0f; }
#pragma unroll
    for (int kk = 0; kk < 4; kk++) {
#pragma unroll
        for (int j = 0; j < 2; j++) {
            int r0 = (8 * kk + q) * P3 + 8 * j + g;
            int r1 = (8 * kk + 4 + q) * P3 + 8 * j + g;
            uint32_t bh0 = u3h[r0], bh1 = u3h[r1];
            uint32_t bl0 = u3l[r0], bl1 = u3l[r1];
            mma16816(acc3[j], a3h[kk], bh0, bh1);
            mma16816(acc3[j], a3l[kk], bh0, bh1);
            mma16816(acc3[j], a3h[kk], bl0, bl1);
        }
    }

    // ======== epilogue 3 + Layer 4 dot + logits ========
    float s0 = 0.0f, s1 = 0.0f;
#pragma unroll
    for (int j = 0; j < 2; j++) {
        float2 bp = *(float2*)&sB3[8 * j + 2 * q];
        float2 wp = *(float2*)&sW4[8 * j + 2 * q];
        float t0 = tanh_fast(acc3[j][0] + bp.x);
        float t1 = tanh_fast(acc3[j][1] + bp.y);
        float t2 = tanh_fast(acc3[j][2] + bp.x);
        float t3 = tanh_fast(acc3[j][3] + bp.y);
        s0 = fmaf(t0, wp.x, fmaf(t1, wp.y, s0));
        s1 = fmaf(t2, wp.x, fmaf(t3, wp.y, s1));
    }
    s0 += __shfl_xor_sync(0xffffffffu, s0, 1);
    s0 += __shfl_xor_sync(0xffffffffu, s0, 2);
    s1 += __shfl_xor_sync(0xffffffffu, s1, 1);
    s1 += __shfl_xor_sync(0xffffffffu, s1, 2);
    if (q == 0) {
        float bb = sB4[0];
        g_logits[base + m0 + g]     = s0 + bb;
        g_logits[base + m0 + g + 8] = s1 + bb;
    }
}

// ---------------------------------------------------------------------------
// Per-segment softmax (global-max subtraction cancels mathematically).
// ---------------------------------------------------------------------------
#define SOFT_THREADS 512

__device__ __forceinline__ float wmax(float v) {
#pragma unroll
    for (int o = 16; o > 0; o >>= 1) v = fmaxf(v, __shfl_xor_sync(0xffffffffu, v, o));
    return v;
}
__device__ __forceinline__ float wsum(float v) {
#pragma unroll
    for (int o = 16; o > 0; o >>= 1) v += __shfl_xor_sync(0xffffffffu, v, o);
    return v;
}
__device__ __forceinline__ int wsumi(int v) {
#pragma unroll
    for (int o = 16; o > 0; o >>= 1) v += __shfl_xor_sync(0xffffffffu, v, o);
    return v;
}

__global__ void __launch_bounds__(SOFT_THREADS)
softmax_seg_kernel(const int* __restrict__ sizes, float* __restrict__ out) {
    __shared__ float shf[16];
    __shared__ int shi[16];
    __shared__ float bcastf;
    __shared__ int bcasti;

    const int b = blockIdx.x, tid = threadIdx.x;
    const int wid = tid >> 5, lid = tid & 31;
    const int nwarp = SOFT_THREADS / 32;

    int part = 0;
    for (int i = tid; i < b; i += SOFT_THREADS) part += sizes[i];
    part = wsumi(part);
    if (lid == 0) shi[wid] = part;
    __syncthreads();
    if (wid == 0) {
        int v = (lid < nwarp) ? shi[lid] : 0;
        v = wsumi(v);
        if (lid == 0) bcasti = v;
    }
    __syncthreads();
    const int off = bcasti;
    const int len = sizes[b];

    float mx = -3.402823466e38f;
    for (int i = tid; i < len; i += SOFT_THREADS) mx = fmaxf(mx, g_logits[off + i]);
    mx = wmax(mx);
    if (lid == 0) shf[wid] = mx;
    __syncthreads();
    if (wid == 0) {
        float v = (lid < nwarp) ? shf[lid] : -3.402823466e38f;
        v = wmax(v);
        if (lid == 0) bcastf = v;
    }
    __syncthreads();
    mx = bcastf;

    float s = 0.0f;
    for (int i = tid; i < len; i += SOFT_THREADS) {
        float e = __expf(g_logits[off + i] - mx);
        out[off + i] = e;
        s += e;
    }
    s = wsum(s);
    __syncthreads();
    if (lid == 0) shf[wid] = s;
    __syncthreads();
    if (wid == 0) {
        float v = (lid < nwarp) ? shf[lid] : 0.0f;
        v = wsum(v);
        if (lid == 0) bcastf = v;
    }
    __syncthreads();
    const float inv = 1.0f / bcastf;

    for (int i = tid; i < len; i += SOFT_THREADS) out[off + i] *= inv;
}

__global__ void tail_sizes_kernel(const int* __restrict__ sizes, float* __restrict__ out,
                                  int n, int basepos) {
    int i = blockIdx.x * blockDim.x + threadIdx.x;
    if (i < n) out[basepos + i] = (float)sizes[i];
}

// ---------------------------------------------------------------------------
extern "C" void kernel_launch(void* const* d_in, const int* in_sizes, int n_in,
                              void* d_out, int out_size) {
    const float* x   = (const float*)d_in[0];
    const int* sizes = (const int*)d_in[1];
    const float* W1  = (const float*)d_in[2];
    const float* b1  = (const float*)d_in[3];
    const float* W2  = (const float*)d_in[4];
    const float* b2  = (const float*)d_in[5];
    const float* W3  = (const float*)d_in[6];
    const float* b3  = (const float*)d_in[7];
    const float* W4  = (const float*)d_in[8];
    const float* b4  = (const float*)d_in[9];
    float* out = (float*)d_out;

    const int total = in_sizes[0] / D_IN;
    const int B     = in_sizes[1];

    cudaFuncSetAttribute(mlp_hmma_kernel, cudaFuncAttributeMaxDynamicSharedMemorySize, SMEM_BYTES);

    mlp_hmma_kernel<<<total / TM, THREADS, SMEM_BYTES>>>(x, W1, b1, W2, b2, W3, b3, W4, b4);
    softmax_seg_kernel<<<B, SOFT_THREADS>>>(sizes, out);

    if (out_size > total) {
        int n = out_size - total;
        tail_sizes_kernel<<<(n + 255) / 256, 256>>>(sizes, out, n, total);
    }
}

// round 5
// speedup vs baseline: 3.0877x; 1.2724x over previous
#include <cuda_runtime.h>
#include <cuda_bf16.h>
#include <stdint.h>

#define THREADS 256
#define TM 128
#define D_IN 64
#define PERSIST_BLOCKS 296   // 2 CTAs per SM x 148 SMs

// ---- smem byte offsets (weights only; X never touches smem) ----
#define W1H_B 0          // 32 k2-rows x 136 u32 pitch = 17408 B
#define W1L_B 17408
#define W2H_B 34816      // 64 x 72 u32 = 18432 B
#define W2L_B 53248
#define W3H_B 71680      // 32 x 24 u32 = 3072 B
#define W3L_B 74752
#define B1_B  77824
#define B2_B  78336
#define B3_B  78592
#define W4_B  78656
#define B4_B  78720
#define SMEM_BYTES 78848

#define P1 136   // u32 pitch (128+8): pitch%32==8 -> conflict-free B frags
#define P2 72    // 64+8
#define P3 24    // 16+8

__device__ float g_logits[1 << 20];

// ---- helpers ----
__device__ __forceinline__ void mma16816(float* c, const uint32_t* a, uint32_t b0, uint32_t b1) {
    asm volatile(
        "mma.sync.aligned.m16n8k16.row.col.f32.bf16.bf16.f32 "
        "{%0,%1,%2,%3}, {%4,%5,%6,%7}, {%8,%9}, {%0,%1,%2,%3};"
        : "+f"(c[0]), "+f"(c[1]), "+f"(c[2]), "+f"(c[3])
        : "r"(a[0]), "r"(a[1]), "r"(a[2]), "r"(a[3]), "r"(b0), "r"(b1));
}

__device__ __forceinline__ uint32_t pack_hi(float a, float b, float& ra, float& rb) {
    __nv_bfloat162 h = __float22bfloat162_rn(make_float2(a, b));
    float2 hf = __bfloat1622float2(h);
    ra = a - hf.x; rb = b - hf.y;
    return *(uint32_t*)&h;
}
__device__ __forceinline__ uint32_t pack2(float a, float b) {
    __nv_bfloat162 h = __float22bfloat162_rn(make_float2(a, b));
    return *(uint32_t*)&h;
}

// accurate fast tanh: 2 MUFU, err ~1e-6
__device__ __forceinline__ float tanh_fast(float x) {
    float e = __expf(2.0f * x);
    return 1.0f - __fdividef(2.0f, e + 1.0f);
}

// ---------------------------------------------------------------------------
// Persistent fused MLP: stage weights once, then stream token tiles.
// 8 warps x 16 tokens per tile, activations entirely in registers,
// zero barriers in the tile loop.
// ---------------------------------------------------------------------------
__global__ void __launch_bounds__(THREADS, 2)
mlp_hmma_kernel(const float* __restrict__ x, int ntiles,
                const float* __restrict__ W1, const float* __restrict__ b1,
                const float* __restrict__ W2, const float* __restrict__ b2,
                const float* __restrict__ W3, const float* __restrict__ b3,
                const float* __restrict__ W4, const float* __restrict__ b4) {
    extern __shared__ char smem[];
    __nv_bfloat16* s1h = (__nv_bfloat16*)(smem + W1H_B);
    __nv_bfloat16* s1l = (__nv_bfloat16*)(smem + W1L_B);
    __nv_bfloat16* s2h = (__nv_bfloat16*)(smem + W2H_B);
    __nv_bfloat16* s2l = (__nv_bfloat16*)(smem + W2L_B);
    __nv_bfloat16* s3h = (__nv_bfloat16*)(smem + W3H_B);
    __nv_bfloat16* s3l = (__nv_bfloat16*)(smem + W3L_B);
    const uint32_t* u1h = (const uint32_t*)(smem + W1H_B);
    const uint32_t* u1l = (const uint32_t*)(smem + W1L_B);
    const uint32_t* u2h = (const uint32_t*)(smem + W2H_B);
    const uint32_t* u2l = (const uint32_t*)(smem + W2L_B);
    const uint32_t* u3h = (const uint32_t*)(smem + W3H_B);
    const uint32_t* u3l = (const uint32_t*)(smem + W3L_B);
    float* sB1 = (float*)(smem + B1_B);
    float* sB2 = (float*)(smem + B2_B);
    float* sB3 = (float*)(smem + B3_B);
    float* sW4 = (float*)(smem + W4_B);
    float* sB4 = (float*)(smem + B4_B);

    const int tid = threadIdx.x;

    // ---- stage weights once: k-pair bf16x2 hi/lo layout ----
#pragma unroll
    for (int it = 0; it < 32; it++) {             // W1: 64k x 128n
        int i = tid + it * THREADS;
        int k = i >> 7, n = i & 127;
        float w = W1[i];
        __nv_bfloat16 h = __float2bfloat16_rn(w);
        __nv_bfloat16 l = __float2bfloat16_rn(w - __bfloat162float(h));
        int idx = (((k >> 1) * P1 + n) << 1) + (k & 1);
        s1h[idx] = h; s1l[idx] = l;
    }
#pragma unroll
    for (int it = 0; it < 32; it++) {             // W2: 128k x 64n
        int i = tid + it * THREADS;
        int k = i >> 6, n = i & 63;
        float w = W2[i];
        __nv_bfloat16 h = __float2bfloat16_rn(w);
        __nv_bfloat16 l = __float2bfloat16_rn(w - __bfloat162float(h));
        int idx = (((k >> 1) * P2 + n) << 1) + (k & 1);
        s2h[idx] = h; s2l[idx] = l;
    }
#pragma unroll
    for (int it = 0; it < 4; it++) {              // W3: 64k x 16n
        int i = tid + it * THREADS;
        int k = i >> 4, n = i & 15;
        float w = W3[i];
        __nv_bfloat16 h = __float2bfloat16_rn(w);
        __nv_bfloat16 l = __float2bfloat16_rn(w - __bfloat162float(h));
        int idx = (((k >> 1) * P3 + n) << 1) + (k & 1);
        s3h[idx] = h; s3l[idx] = l;
    }
    if (tid < 128) sB1[tid] = b1[tid];
    if (tid < 64)  sB2[tid] = b2[tid];
    if (tid < 16)  { sB3[tid] = b3[tid]; sW4[tid] = W4[tid]; }
    if (tid == 0)  sB4[0] = b4[0];
    __syncthreads();

    const int wid = tid >> 5, lid = tid & 31;
    const int m0 = wid * 16;
    const int g  = lid >> 2;        // group row 0..7
    const int q  = lid & 3;         // quad col 0..3
    const float bb4 = b4[0];

    // -------- persistent tile loop: no barriers, warps fully independent ----
    for (int tile = blockIdx.x; tile < ntiles; tile += gridDim.x) {
        const long long base = (long long)tile * TM;
        const float* xw = x + (base + m0) * D_IN;

        // ---- A1 fragments straight from gmem ----
        uint32_t a1h[4][4], a1l[4][4];
#pragma unroll
        for (int kk = 0; kk < 4; kk++) {
            int c0 = q * 2 + 16 * kk;
            float2 p00 = *(const float2*)&xw[g * D_IN + c0];
            float2 p10 = *(const float2*)&xw[(g + 8) * D_IN + c0];
            float2 p01 = *(const float2*)&xw[g * D_IN + c0 + 8];
            float2 p11 = *(const float2*)&xw[(g + 8) * D_IN + c0 + 8];
            float r0, r1;
            a1h[kk][0] = pack_hi(p00.x, p00.y, r0, r1); a1l[kk][0] = pack2(r0, r1);
            a1h[kk][1] = pack_hi(p10.x, p10.y, r0, r1); a1l[kk][1] = pack2(r0, r1);
            a1h[kk][2] = pack_hi(p01.x, p01.y, r0, r1); a1l[kk][2] = pack2(r0, r1);
            a1h[kk][3] = pack_hi(p11.x, p11.y, r0, r1); a1l[kk][3] = pack2(r0, r1);
        }

        // ======== Layer 1: [16x64] @ [64x128], j-pair outer ========
        uint32_t a2h[8][4], a2l[8][4];
#pragma unroll
        for (int jp = 0; jp < 8; jp++) {
            float accA[4] = {0.f, 0.f, 0.f, 0.f};
            float accB[4] = {0.f, 0.f, 0.f, 0.f};
            const int j0 = 2 * jp, j1 = 2 * jp + 1;
#pragma unroll
            for (int kk = 0; kk < 4; kk++) {
                int rA0 = (8 * kk + q) * P1 + 8 * j0 + g;
                int rA1 = rA0 + 4 * P1;
                int rB0 = (8 * kk + q) * P1 + 8 * j1 + g;
                int rB1 = rB0 + 4 * P1;
                uint32_t bhA0 = u1h[rA0], bhA1 = u1h[rA1];
                uint32_t blA0 = u1l[rA0], blA1 = u1l[rA1];
                uint32_t bhB0 = u1h[rB0], bhB1 = u1h[rB1];
                uint32_t blB0 = u1l[rB0], blB1 = u1l[rB1];
                mma16816(accA, a1h[kk], bhA0, bhA1);
                mma16816(accB, a1h[kk], bhB0, bhB1);
                mma16816(accA, a1l[kk], bhA0, bhA1);
                mma16816(accB, a1l[kk], bhB0, bhB1);
                mma16816(accA, a1h[kk], blA0, blA1);
                mma16816(accB, a1h[kk], blB0, blB1);
            }
            // epilogue -> A2 fragment jp
            float2 bpA = *(float2*)&sB1[8 * j0 + 2 * q];
            float2 bpB = *(float2*)&sB1[8 * j1 + 2 * q];
            float t0 = tanh_fast(accA[0] + bpA.x);
            float t1 = tanh_fast(accA[1] + bpA.y);
            float t2 = tanh_fast(accA[2] + bpA.x);
            float t3 = tanh_fast(accA[3] + bpA.y);
            float u0 = tanh_fast(accB[0] + bpB.x);
            float u1 = tanh_fast(accB[1] + bpB.y);
            float u2 = tanh_fast(accB[2] + bpB.x);
            float u3 = tanh_fast(accB[3] + bpB.y);
            float r0, r1;
            a2h[jp][0] = pack_hi(t0, t1, r0, r1); a2l[jp][0] = pack2(r0, r1);
            a2h[jp][1] = pack_hi(t2, t3, r0, r1); a2l[jp][1] = pack2(r0, r1);
            a2h[jp][2] = pack_hi(u0, u1, r0, r1); a2l[jp][2] = pack2(r0, r1);
            a2h[jp][3] = pack_hi(u2, u3, r0, r1); a2l[jp][3] = pack2(r0, r1);
        }

        // ======== Layer 2: [16x128] @ [128x64], j-pair outer ========
        uint32_t a3h[4][4], a3l[4][4];
#pragma unroll
        for (int jp = 0; jp < 4; jp++) {
            float accA[4] = {0.f, 0.f, 0.f, 0.f};
            float accB[4] = {0.f, 0.f, 0.f, 0.f};
            const int j0 = 2 * jp, j1 = 2 * jp + 1;
#pragma unroll
            for (int kk = 0; kk < 8; kk++) {
                int rA0 = (8 * kk + q) * P2 + 8 * j0 + g;
                int rA1 = rA0 + 4 * P2;
                int rB0 = (8 * kk + q) * P2 + 8 * j1 + g;
                int rB1 = rB0 + 4 * P2;
                uint32_t bhA0 = u2h[rA0], bhA1 = u2h[rA1];
                uint32_t blA0 = u2l[rA0], blA1 = u2l[rA1];
                uint32_t bhB0 = u2h[rB0], bhB1 = u2h[rB1];
                uint32_t blB0 = u2l[rB0], blB1 = u2l[rB1];
                mma16816(accA, a2h[kk], bhA0, bhA1);
                mma16816(accB, a2h[kk], bhB0, bhB1);
                mma16816(accA, a2l[kk], bhA0, bhA1);
                mma16816(accB, a2l[kk], bhB0, bhB1);
                mma16816(accA, a2h[kk], blA0, blA1);
                mma16816(accB, a2h[kk], blB0, blB1);
            }
            float2 bpA = *(float2*)&sB2[8 * j0 + 2 * q];
            float2 bpB = *(float2*)&sB2[8 * j1 + 2 * q];
            float t0 = tanh_fast(accA[0] + bpA.x);
            float t1 = tanh_fast(accA[1] + bpA.y);
            float t2 = tanh_fast(accA[2] + bpA.x);
            float t3 = tanh_fast(accA[3] + bpA.y);
            float u0 = tanh_fast(accB[0] + bpB.x);
            float u1 = tanh_fast(accB[1] + bpB.y);
            float u2 = tanh_fast(accB[2] + bpB.x);
            float u3 = tanh_fast(accB[3] + bpB.y);
            float r0, r1;
            a3h[jp][0] = pack_hi(t0, t1, r0, r1); a3l[jp][0] = pack2(r0, r1);
            a3h[jp][1] = pack_hi(t2, t3, r0, r1); a3l[jp][1] = pack2(r0, r1);
            a3h[jp][2] = pack_hi(u0, u1, r0, r1); a3l[jp][2] = pack2(r0, r1);
            a3h[jp][3] = pack_hi(u2, u3, r0, r1); a3l[jp][3] = pack2(r0, r1);
        }

        // ======== Layer 3: [16x64] @ [64x16] (single j-pair) ========
        float accA[4] = {0.f, 0.f, 0.f, 0.f};
        float accB[4] = {0.f, 0.f, 0.f, 0.f};
#pragma unroll
        for (int kk = 0; kk < 4; kk++) {
            int rA0 = (8 * kk + q) * P3 + g;
            int rA1 = rA0 + 4 * P3;
            int rB0 = rA0 + 8;
            int rB1 = rA1 + 8;
            uint32_t bhA0 = u3h[rA0], bhA1 = u3h[rA1];
            uint32_t blA0 = u3l[rA0], blA1 = u3l[rA1];
            uint32_t bhB0 = u3h[rB0], bhB1 = u3h[rB1];
            uint32_t blB0 = u3l[rB0], blB1 = u3l[rB1];
            mma16816(accA, a3h[kk], bhA0, bhA1);
            mma16816(accB, a3h[kk], bhB0, bhB1);
            mma16816(accA, a3l[kk], bhA0, bhA1);
            mma16816(accB, a3l[kk], bhB0, bhB1);
            mma16816(accA, a3h[kk], blA0, blA1);
            mma16816(accB, a3h[kk], blB0, blB1);
        }

        // ======== epilogue 3 + Layer 4 dot + logits ========
        float2 bpA = *(float2*)&sB3[2 * q];
        float2 bpB = *(float2*)&sB3[8 + 2 * q];
        float2 wpA = *(float2*)&sW4[2 * q];
        float2 wpB = *(float2*)&sW4[8 + 2 * q];
        float s0 = 0.0f, s1 = 0.0f;
        s0 = fmaf(tanh_fast(accA[0] + bpA.x), wpA.x, s0);
        s0 = fmaf(tanh_fast(accA[1] + bpA.y), wpA.y, s0);
        s1 = fmaf(tanh_fast(accA[2] + bpA.x), wpA.x, s1);
        s1 = fmaf(tanh_fast(accA[3] + bpA.y), wpA.y, s1);
        s0 = fmaf(tanh_fast(accB[0] + bpB.x), wpB.x, s0);
        s0 = fmaf(tanh_fast(accB[1] + bpB.y), wpB.y, s0);
        s1 = fmaf(tanh_fast(accB[2] + bpB.x), wpB.x, s1);
        s1 = fmaf(tanh_fast(accB[3] + bpB.y), wpB.y, s1);
        s0 += __shfl_xor_sync(0xffffffffu, s0, 1);
        s0 += __shfl_xor_sync(0xffffffffu, s0, 2);
        s1 += __shfl_xor_sync(0xffffffffu, s1, 1);
        s1 += __shfl_xor_sync(0xffffffffu, s1, 2);
        if (q == 0) {
            g_logits[base + m0 + g]     = s0 + bb4;
            g_logits[base + m0 + g + 8] = s1 + bb4;
        }
    }
}

// ---------------------------------------------------------------------------
// Per-segment softmax (global-max subtraction cancels mathematically).
// ---------------------------------------------------------------------------
#define SOFT_THREADS 512

__device__ __forceinline__ float wmax(float v) {
#pragma unroll
    for (int o = 16; o > 0; o >>= 1) v = fmaxf(v, __shfl_xor_sync(0xffffffffu, v, o));
    return v;
}
__device__ __forceinline__ float wsum(float v) {
#pragma unroll
    for (int o = 16; o > 0; o >>= 1) v += __shfl_xor_sync(0xffffffffu, v, o);
    return v;
}
__device__ __forceinline__ int wsumi(int v) {
#pragma unroll
    for (int o = 16; o > 0; o >>= 1) v += __shfl_xor_sync(0xffffffffu, v, o);
    return v;
}

__global__ void __launch_bounds__(SOFT_THREADS)
softmax_seg_kernel(const int* __restrict__ sizes, float* __restrict__ out) {
    __shared__ float shf[16];
    __shared__ int shi[16];
    __shared__ float bcastf;
    __shared__ int bcasti;

    const int b = blockIdx.x, tid = threadIdx.x;
    const int wid = tid >> 5, lid = tid & 31;
    const int nwarp = SOFT_THREADS / 32;

    int part = 0;
    for (int i = tid; i < b; i += SOFT_THREADS) part += sizes[i];
    part = wsumi(part);
    if (lid == 0) shi[wid] = part;
    __syncthreads();
    if (wid == 0) {
        int v = (lid < nwarp) ? shi[lid] : 0;
        v = wsumi(v);
        if (lid == 0) bcasti = v;
    }
    __syncthreads();
    const int off = bcasti;
    const int len = sizes[b];

    float mx = -3.402823466e38f;
    for (int i = tid; i < len; i += SOFT_THREADS) mx = fmaxf(mx, g_logits[off + i]);
    mx = wmax(mx);
    if (lid == 0) shf[wid] = mx;
    __syncthreads();
    if (wid == 0) {
        float v = (lid < nwarp) ? shf[lid] : -3.402823466e38f;
        v = wmax(v);
        if (lid == 0) bcastf = v;
    }
    __syncthreads();
    mx = bcastf;

    float s = 0.0f;
    for (int i = tid; i < len; i += SOFT_THREADS) {
        float e = __expf(g_logits[off + i] - mx);
        out[off + i] = e;
        s += e;
    }
    s = wsum(s);
    __syncthreads();
    if (lid == 0) shf[wid] = s;
    __syncthreads();
    if (wid == 0) {
        float v = (lid < nwarp) ? shf[lid] : 0.0f;
        v = wsum(v);
        if (lid == 0) bcastf = v;
    }
    __syncthreads();
    const float inv = 1.0f / bcastf;

    for (int i = tid; i < len; i += SOFT_THREADS) out[off + i] *= inv;
}

__global__ void tail_sizes_kernel(const int* __restrict__ sizes, float* __restrict__ out,
                                  int n, int basepos) {
    int i = blockIdx.x * blockDim.x + threadIdx.x;
    if (i < n) out[basepos + i] = (float)sizes[i];
}

// ---------------------------------------------------------------------------
extern "C" void kernel_launch(void* const* d_in, const int* in_sizes, int n_in,
                              void* d_out, int out_size) {
    const float* x   = (const float*)d_in[0];
    const int* sizes = (const int*)d_in[1];
    const float* W1  = (const float*)d_in[2];
    const float* b1  = (const float*)d_in[3];
    const float* W2  = (const float*)d_in[4];
    const float* b2  = (const float*)d_in[5];
    const float* W3  = (const float*)d_in[6];
    const float* b3  = (const float*)d_in[7];
    const float* W4  = (const float*)d_in[8];
    const float* b4  = (const float*)d_in[9];
    float* out = (float*)d_out;

    const int total  = in_sizes[0] / D_IN;
    const int B      = in_sizes[1];
    const int ntiles = total / TM;

    cudaFuncSetAttribute(mlp_hmma_kernel, cudaFuncAttributeMaxDynamicSharedMemorySize, SMEM_BYTES);

    int blocks = PERSIST_BLOCKS < ntiles ? PERSIST_BLOCKS : ntiles;
    mlp_hmma_kernel<<<blocks, THREADS, SMEM_BYTES>>>(x, ntiles, W1, b1, W2, b2, W3, b3, W4, b4);
    softmax_seg_kernel<<<B, SOFT_THREADS>>>(sizes, out);

    if (out_size > total) {
        int n = out_size - total;
        tail_sizes_kernel<<<(n + 255) / 256, 256>>>(sizes, out, n, total);
    }
}

// round 6
// speedup vs baseline: 3.5870x; 1.1617x over previous
#include <cuda_runtime.h>
#include <cuda_bf16.h>
#include <stdint.h>

#define THREADS 256
#define TM 128
#define D_IN 64
#define PERSIST_BLOCKS 296   // 2 CTAs per SM x 148 SMs

// ---- smem byte offsets: LDSM-tiled weights (8n x 8k bf16 tiles, 16B rows) ----
#define W1H_B 0          // 32 blocks x 512B = 16384
#define W1L_B 16384
#define W2H_B 32768      // 32 blocks x 512B
#define W2L_B 49152
#define W3H_B 65536      // 4 blocks x 512B = 2048
#define W3L_B 67584
#define B1_B  69632      // scaled biases (f32)
#define B2_B  70144
#define B3_B  70400
#define W4_B  70464
#define SMEM_BYTES 70656

#define TANH_C 2.885390081777927f   // 2 * log2(e)

__device__ float g_logits[1 << 20];

// ---- helpers ----
__device__ __forceinline__ uint32_t smem_u32(const void* p) {
    uint32_t a;
    asm("{ .reg .u64 t; cvta.to.shared.u64 t, %1; cvt.u32.u64 %0, t; }" : "=r"(a) : "l"(p));
    return a;
}
__device__ __forceinline__ void mma16816(float* c, const uint32_t* a, uint32_t b0, uint32_t b1) {
    asm volatile(
        "mma.sync.aligned.m16n8k16.row.col.f32.bf16.bf16.f32 "
        "{%0,%1,%2,%3}, {%4,%5,%6,%7}, {%8,%9}, {%0,%1,%2,%3};"
        : "+f"(c[0]), "+f"(c[1]), "+f"(c[2]), "+f"(c[3])
        : "r"(a[0]), "r"(a[1]), "r"(a[2]), "r"(a[3]), "r"(b0), "r"(b1));
}
__device__ __forceinline__ void ldsm4(uint32_t* d, uint32_t addr) {
    asm volatile("ldmatrix.sync.aligned.m8n8.x4.shared.b16 {%0,%1,%2,%3}, [%4];"
        : "=r"(d[0]), "=r"(d[1]), "=r"(d[2]), "=r"(d[3]) : "r"(addr));
}
__device__ __forceinline__ uint32_t pack_hi(float a, float b, float& ra, float& rb) {
    __nv_bfloat162 h = __float22bfloat162_rn(make_float2(a, b));
    float2 hf = __bfloat1622float2(h);
    ra = a - hf.x; rb = b - hf.y;
    return *(uint32_t*)&h;
}
__device__ __forceinline__ uint32_t pack2(float a, float b) {
    __nv_bfloat162 h = __float22bfloat162_rn(make_float2(a, b));
    return *(uint32_t*)&h;
}
// tanh(acc + b) with pre-scaled bias bs = b * 2log2e: 5 instrs, err ~1e-6
__device__ __forceinline__ float tanh_b(float acc, float bs) {
    float t = fmaf(acc, TANH_C, bs);
    float e; asm("ex2.approx.ftz.f32 %0, %1;" : "=f"(e) : "f"(t));
    float d = e + 1.0f;
    float r; asm("rcp.approx.ftz.f32 %0, %1;" : "=f"(r) : "f"(d));
    return fmaf(-2.0f, r, 1.0f);
}

// ---------------------------------------------------------------------------
// Persistent fused MLP: stage weights once (LDSM tiling), stream token tiles.
// 8 warps x 16 tokens per tile, activations in registers, no loop barriers.
// ---------------------------------------------------------------------------
__global__ void __launch_bounds__(THREADS, 2)
mlp_hmma_kernel(const float* __restrict__ x, int ntiles,
                const float* __restrict__ W1, const float* __restrict__ b1,
                const float* __restrict__ W2, const float* __restrict__ b2,
                const float* __restrict__ W3, const float* __restrict__ b3,
                const float* __restrict__ W4, const float* __restrict__ b4) {
    extern __shared__ char smem[];
    float* sB1 = (float*)(smem + B1_B);
    float* sB2 = (float*)(smem + B2_B);
    float* sB3 = (float*)(smem + B3_B);
    float* sW4 = (float*)(smem + W4_B);

    const int tid = threadIdx.x;

    // ---- stage weights once into LDSM tile layout (hi/lo bf16 split) ----
    // block(jp,kk) = 4 matrices (j01,khalf), each 8 n-rows x 16B (8 k bf16)
#pragma unroll
    for (int it = 0; it < 32; it++) {             // W1: [64k x 128n]
        int i = tid + it * THREADS;
        int k = i >> 7, n = i & 127;
        float w = W1[i];
        __nv_bfloat16 h = __float2bfloat16_rn(w);
        __nv_bfloat16 l = __float2bfloat16_rn(w - __bfloat162float(h));
        int kk = k >> 4, khalf = (k >> 3) & 1, kin = k & 7;
        int jp = n >> 4, j01 = (n >> 3) & 1, nin = n & 7;
        uint32_t off = ((((jp << 2) + kk) * 4 + j01 * 2 + khalf) << 7) + (nin << 4) + (kin << 1);
        *(__nv_bfloat16*)(smem + W1H_B + off) = h;
        *(__nv_bfloat16*)(smem + W1L_B + off) = l;
    }
#pragma unroll
    for (int it = 0; it < 32; it++) {             // W2: [128k x 64n]
        int i = tid + it * THREADS;
        int k = i >> 6, n = i & 63;
        float w = W2[i];
        __nv_bfloat16 h = __float2bfloat16_rn(w);
        __nv_bfloat16 l = __float2bfloat16_rn(w - __bfloat162float(h));
        int kk = k >> 4, khalf = (k >> 3) & 1, kin = k & 7;
        int jp = n >> 4, j01 = (n >> 3) & 1, nin = n & 7;
        uint32_t off = ((((jp << 3) + kk) * 4 + j01 * 2 + khalf) << 7) + (nin << 4) + (kin << 1);
        *(__nv_bfloat16*)(smem + W2H_B + off) = h;
        *(__nv_bfloat16*)(smem + W2L_B + off) = l;
    }
#pragma unroll
    for (int it = 0; it < 4; it++) {              // W3: [64k x 16n]
        int i = tid + it * THREADS;
        int k = i >> 4, n = i & 15;
        float w = W3[i];
        __nv_bfloat16 h = __float2bfloat16_rn(w);
        __nv_bfloat16 l = __float2bfloat16_rn(w - __bfloat162float(h));
        int kk = k >> 4, khalf = (k >> 3) & 1, kin = k & 7;
        int j01 = (n >> 3) & 1, nin = n & 7;
        uint32_t off = (((kk << 2) + j01 * 2 + khalf) << 7) + (nin << 4) + (kin << 1);
        *(__nv_bfloat16*)(smem + W3H_B + off) = h;
        *(__nv_bfloat16*)(smem + W3L_B + off) = l;
    }
    if (tid < 128) sB1[tid] = b1[tid] * TANH_C;
    if (tid < 64)  sB2[tid] = b2[tid] * TANH_C;
    if (tid < 16)  { sB3[tid] = b3[tid] * TANH_C; sW4[tid] = W4[tid]; }
    __syncthreads();

    const int wid = tid >> 5, lid = tid & 31;
    const int m0 = wid * 16;
    const int g  = lid >> 2;        // group row 0..7
    const int q  = lid & 3;         // quad col 0..3
    const float bb4 = b4[0];

    const uint32_t smb = smem_u32(smem);
    const uint32_t lane16 = (uint32_t)lid << 4;
    const uint32_t w1h = smb + W1H_B + lane16, w1l = smb + W1L_B + lane16;
    const uint32_t w2h = smb + W2H_B + lane16, w2l = smb + W2L_B + lane16;
    const uint32_t w3h = smb + W3H_B + lane16, w3l = smb + W3L_B + lane16;

    // -------- persistent tile loop --------
    for (int tile = blockIdx.x; tile < ntiles; tile += gridDim.x) {
        const long long base = (long long)tile * TM;
        const float* xw = x + (base + m0) * D_IN;

        // ---- A1 fragments straight from gmem ----
        uint32_t a1h[4][4], a1l[4][4];
#pragma unroll
        for (int kk = 0; kk < 4; kk++) {
            int c0 = q * 2 + 16 * kk;
            float2 p00 = *(const float2*)&xw[g * D_IN + c0];
            float2 p10 = *(const float2*)&xw[(g + 8) * D_IN + c0];
            float2 p01 = *(const float2*)&xw[g * D_IN + c0 + 8];
            float2 p11 = *(const float2*)&xw[(g + 8) * D_IN + c0 + 8];
            float r0, r1;
            a1h[kk][0] = pack_hi(p00.x, p00.y, r0, r1); a1l[kk][0] = pack2(r0, r1);
            a1h[kk][1] = pack_hi(p10.x, p10.y, r0, r1); a1l[kk][1] = pack2(r0, r1);
            a1h[kk][2] = pack_hi(p01.x, p01.y, r0, r1); a1l[kk][2] = pack2(r0, r1);
            a1h[kk][3] = pack_hi(p11.x, p11.y, r0, r1); a1l[kk][3] = pack2(r0, r1);
        }

        // ======== Layer 1: [16x64] @ [64x128] ========
        uint32_t a2h[8][4], a2l[8][4];
#pragma unroll
        for (int jp = 0; jp < 8; jp++) {
            float accA[4] = {0.f, 0.f, 0.f, 0.f};
            float accB[4] = {0.f, 0.f, 0.f, 0.f};
#pragma unroll
            for (int kk = 0; kk < 4; kk++) {
                uint32_t bh[4], bl[4];
                ldsm4(bh, w1h + (uint32_t)(jp * 2048 + kk * 512));
                ldsm4(bl, w1l + (uint32_t)(jp * 2048 + kk * 512));
                mma16816(accA, a1h[kk], bh[0], bh[1]);
                mma16816(accB, a1h[kk], bh[2], bh[3]);
                mma16816(accA, a1l[kk], bh[0], bh[1]);
                mma16816(accB, a1l[kk], bh[2], bh[3]);
                mma16816(accA, a1h[kk], bl[0], bl[1]);
                mma16816(accB, a1h[kk], bl[2], bl[3]);
            }
            float2 bpA = *(float2*)&sB1[16 * jp + 2 * q];
            float2 bpB = *(float2*)&sB1[16 * jp + 8 + 2 * q];
            float t0 = tanh_b(accA[0], bpA.x);
            float t1 = tanh_b(accA[1], bpA.y);
            float t2 = tanh_b(accA[2], bpA.x);
            float t3 = tanh_b(accA[3], bpA.y);
            float u0 = tanh_b(accB[0], bpB.x);
            float u1 = tanh_b(accB[1], bpB.y);
            float u2 = tanh_b(accB[2], bpB.x);
            float u3 = tanh_b(accB[3], bpB.y);
            float r0, r1;
            a2h[jp][0] = pack_hi(t0, t1, r0, r1); a2l[jp][0] = pack2(r0, r1);
            a2h[jp][1] = pack_hi(t2, t3, r0, r1); a2l[jp][1] = pack2(r0, r1);
            a2h[jp][2] = pack_hi(u0, u1, r0, r1); a2l[jp][2] = pack2(r0, r1);
            a2h[jp][3] = pack_hi(u2, u3, r0, r1); a2l[jp][3] = pack2(r0, r1);
        }

        // ======== Layer 2: [16x128] @ [128x64] ========
        uint32_t a3h[4][4], a3l[4][4];
#pragma unroll
        for (int jp = 0; jp < 4; jp++) {
            float accA[4] = {0.f, 0.f, 0.f, 0.f};
            float accB[4] = {0.f, 0.f, 0.f, 0.f};
#pragma unroll
            for (int kk = 0; kk < 8; kk++) {
                uint32_t bh[4], bl[4];
                ldsm4(bh, w2h + (uint32_t)(jp * 4096 + kk * 512));
                ldsm4(bl, w2l + (uint32_t)(jp * 4096 + kk * 512));
                mma16816(accA, a2h[kk], bh[0], bh[1]);
                mma16816(accB, a2h[kk], bh[2], bh[3]);
                mma16816(accA, a2l[kk], bh[0], bh[1]);
                mma16816(accB, a2l[kk], bh[2], bh[3]);
                mma16816(accA, a2h[kk], bl[0], bl[1]);
                mma16816(accB, a2h[kk], bl[2], bl[3]);
            }
            float2 bpA = *(float2*)&sB2[16 * jp + 2 * q];
            float2 bpB = *(float2*)&sB2[16 * jp + 8 + 2 * q];
            float t0 = tanh_b(accA[0], bpA.x);
            float t1 = tanh_b(accA[1], bpA.y);
            float t2 = tanh_b(accA[2], bpA.x);
            float t3 = tanh_b(accA[3], bpA.y);
            float u0 = tanh_b(accB[0], bpB.x);
            float u1 = tanh_b(accB[1], bpB.y);
            float u2 = tanh_b(accB[2], bpB.x);
            float u3 = tanh_b(accB[3], bpB.y);
            float r0, r1;
            a3h[jp][0] = pack_hi(t0, t1, r0, r1); a3l[jp][0] = pack2(r0, r1);
            a3h[jp][1] = pack_hi(t2, t3, r0, r1); a3l[jp][1] = pack2(r0, r1);
            a3h[jp][2] = pack_hi(u0, u1, r0, r1); a3l[jp][2] = pack2(r0, r1);
            a3h[jp][3] = pack_hi(u2, u3, r0, r1); a3l[jp][3] = pack2(r0, r1);
        }

        // ======== Layer 3: [16x64] @ [64x16] ========
        float accA[4] = {0.f, 0.f, 0.f, 0.f};
        float accB[4] = {0.f, 0.f, 0.f, 0.f};
#pragma unroll
        for (int kk = 0; kk < 4; kk++) {
            uint32_t bh[4], bl[4];
            ldsm4(bh, w3h + (uint32_t)(kk * 512));
            ldsm4(bl, w3l + (uint32_t)(kk * 512));
            mma16816(accA, a3h[kk], bh[0], bh[1]);
            mma16816(accB, a3h[kk], bh[2], bh[3]);
            mma16816(accA, a3l[kk], bh[0], bh[1]);
            mma16816(accB, a3l[kk], bh[2], bh[3]);
            mma16816(accA, a3h[kk], bl[0], bl[1]);
            mma16816(accB, a3h[kk], bl[2], bl[3]);
        }

        // ======== epilogue 3 + Layer 4 dot + logits ========
        float2 bpA = *(float2*)&sB3[2 * q];
        float2 bpB = *(float2*)&sB3[8 + 2 * q];
        float2 wpA = *(float2*)&sW4[2 * q];
        float2 wpB = *(float2*)&sW4[8 + 2 * q];
        float s0 = 0.0f, s1 = 0.0f;
        s0 = fmaf(tanh_b(accA[0], bpA.x), wpA.x, s0);
        s0 = fmaf(tanh_b(accA[1], bpA.y), wpA.y, s0);
        s1 = fmaf(tanh_b(accA[2], bpA.x), wpA.x, s1);
        s1 = fmaf(tanh_b(accA[3], bpA.y), wpA.y, s1);
        s0 = fmaf(tanh_b(accB[0], bpB.x), wpB.x, s0);
        s0 = fmaf(tanh_b(accB[1], bpB.y), wpB.y, s0);
        s1 = fmaf(tanh_b(accB[2], bpB.x), wpB.x, s1);
        s1 = fmaf(tanh_b(accB[3], bpB.y), wpB.y, s1);
        s0 += __shfl_xor_sync(0xffffffffu, s0, 1);
        s0 += __shfl_xor_sync(0xffffffffu, s0, 2);
        s1 += __shfl_xor_sync(0xffffffffu, s1, 1);
        s1 += __shfl_xor_sync(0xffffffffu, s1, 2);
        if (q == 0) {
            g_logits[base + m0 + g]     = s0 + bb4;
            g_logits[base + m0 + g + 8] = s1 + bb4;
        }
    }
}

// ---------------------------------------------------------------------------
// Per-segment softmax (global-max subtraction cancels mathematically).
// ---------------------------------------------------------------------------
#define SOFT_THREADS 512

__device__ __forceinline__ float wmax(float v) {
#pragma unroll
    for (int o = 16; o > 0; o >>= 1) v = fmaxf(v, __shfl_xor_sync(0xffffffffu, v, o));
    return v;
}
__device__ __forceinline__ float wsum(float v) {
#pragma unroll
    for (int o = 16; o > 0; o >>= 1) v += __shfl_xor_sync(0xffffffffu, v, o);
    return v;
}
__device__ __forceinline__ int wsumi(int v) {
#pragma unroll
    for (int o = 16; o > 0; o >>= 1) v += __shfl_xor_sync(0xffffffffu, v, o);
    return v;
}

__global__ void __launch_bounds__(SOFT_THREADS)
softmax_seg_kernel(const int* __restrict__ sizes, float* __restrict__ out) {
    __shared__ float shf[16];
    __shared__ int shi[16];
    __shared__ float bcastf;
    __shared__ int bcasti;

    const int b = blockIdx.x, tid = threadIdx.x;
    const int wid = tid >> 5, lid = tid & 31;
    const int nwarp = SOFT_THREADS / 32;

    int part = 0;
    for (int i = tid; i < b; i += SOFT_THREADS) part += sizes[i];
    part = wsumi(part);
    if (lid == 0) shi[wid] = part;
    __syncthreads();
    if (wid == 0) {
        int v = (lid < nwarp) ? shi[lid] : 0;
        v = wsumi(v);
        if (lid == 0) bcasti = v;
    }
    __syncthreads();
    const int off = bcasti;
    const int len = sizes[b];

    float mx = -3.402823466e38f;
    for (int i = tid; i < len; i += SOFT_THREADS) mx = fmaxf(mx, g_logits[off + i]);
    mx = wmax(mx);
    if (lid == 0) shf[wid] = mx;
    __syncthreads();
    if (wid == 0) {
        float v = (lid < nwarp) ? shf[lid] : -3.402823466e38f;
        v = wmax(v);
        if (lid == 0) bcastf = v;
    }
    __syncthreads();
    mx = bcastf;

    float s = 0.0f;
    for (int i = tid; i < len; i += SOFT_THREADS) {
        float e = __expf(g_logits[off + i] - mx);
        out[off + i] = e;
        s += e;
    }
    s = wsum(s);
    __syncthreads();
    if (lid == 0) shf[wid] = s;
    __syncthreads();
    if (wid == 0) {
        float v = (lid < nwarp) ? shf[lid] : 0.0f;
        v = wsum(v);
        if (lid == 0) bcastf = v;
    }
    __syncthreads();
    const float inv = 1.0f / bcastf;

    for (int i = tid; i < len; i += SOFT_THREADS) out[off + i] *= inv;
}

__global__ void tail_sizes_kernel(const int* __restrict__ sizes, float* __restrict__ out,
                                  int n, int basepos) {
    int i = blockIdx.x * blockDim.x + threadIdx.x;
    if (i < n) out[basepos + i] = (float)sizes[i];
}

// ---------------------------------------------------------------------------
extern "C" void kernel_launch(void* const* d_in, const int* in_sizes, int n_in,
                              void* d_out, int out_size) {
    const float* x   = (const float*)d_in[0];
    const int* sizes = (const int*)d_in[1];
    const float* W1  = (const float*)d_in[2];
    const float* b1  = (const float*)d_in[3];
    const float* W2  = (const float*)d_in[4];
    const float* b2  = (const float*)d_in[5];
    const float* W3  = (const float*)d_in[6];
    const float* b3  = (const float*)d_in[7];
    const float* W4  = (const float*)d_in[8];
    const float* b4  = (const float*)d_in[9];
    float* out = (float*)d_out;

    const int total  = in_sizes[0] / D_IN;
    const int B      = in_sizes[1];
    const int ntiles = total / TM;

    cudaFuncSetAttribute(mlp_hmma_kernel, cudaFuncAttributeMaxDynamicSharedMemorySize, SMEM_BYTES);

    int blocks = PERSIST_BLOCKS < ntiles ? PERSIST_BLOCKS : ntiles;
    mlp_hmma_kernel<<<blocks, THREADS, SMEM_BYTES>>>(x, ntiles, W1, b1, W2, b2, W3, b3, W4, b4);
    softmax_seg_kernel<<<B, SOFT_THREADS>>>(sizes, out);

    if (out_size > total) {
        int n = out_size - total;
        tail_sizes_kernel<<<(n + 255) / 256, 256>>>(sizes, out, n, total);
    }
}

// round 7
// speedup vs baseline: 3.6314x; 1.0124x over previous
#include <cuda_runtime.h>
#include <cuda_bf16.h>
#include <stdint.h>

#define THREADS 256
#define TM 128
#define D_IN 64
#define PERSIST_BLOCKS 296   // 2 CTAs per SM x 148 SMs

// ---- smem byte offsets: LDSM-tiled weights (8n x 8k bf16 tiles, 16B rows) ----
#define W1H_B 0          // 32 blocks x 512B = 16384
#define W1L_B 16384
#define W2H_B 32768      // 32 blocks x 512B
#define W2L_B 49152
#define W3H_B 65536      // 4 blocks x 512B = 2048
#define W3L_B 67584
#define B1_B  69632      // scaled biases (f32)
#define B2_B  70144
#define B3_B  70400
#define W4_B  70464
#define SMEM_BYTES 70656

#define TANH_C 2.885390081777927f   // 2 * log2(e)

__device__ float g_logits[1 << 20];

// ---- helpers ----
__device__ __forceinline__ uint32_t smem_u32(const void* p) {
    uint32_t a;
    asm("{ .reg .u64 t; cvta.to.shared.u64 t, %1; cvt.u32.u64 %0, t; }" : "=r"(a) : "l"(p));
    return a;
}
__device__ __forceinline__ void mma16816(float* c, const uint32_t* a, uint32_t b0, uint32_t b1) {
    asm volatile(
        "mma.sync.aligned.m16n8k16.row.col.f32.bf16.bf16.f32 "
        "{%0,%1,%2,%3}, {%4,%5,%6,%7}, {%8,%9}, {%0,%1,%2,%3};"
        : "+f"(c[0]), "+f"(c[1]), "+f"(c[2]), "+f"(c[3])
        : "r"(a[0]), "r"(a[1]), "r"(a[2]), "r"(a[3]), "r"(b0), "r"(b1));
}
__device__ __forceinline__ void ldsm4(uint32_t* d, uint32_t addr) {
    asm volatile("ldmatrix.sync.aligned.m8n8.x4.shared.b16 {%0,%1,%2,%3}, [%4];"
        : "=r"(d[0]), "=r"(d[1]), "=r"(d[2]), "=r"(d[3]) : "r"(addr));
}
__device__ __forceinline__ void prefetchL2(const void* p) {
    asm volatile("prefetch.global.L2 [%0];" :: "l"(p));
}
__device__ __forceinline__ uint32_t pack_hi(float a, float b, float& ra, float& rb) {
    __nv_bfloat162 h = __float22bfloat162_rn(make_float2(a, b));
    float2 hf = __bfloat1622float2(h);
    ra = a - hf.x; rb = b - hf.y;
    return *(uint32_t*)&h;
}
__device__ __forceinline__ uint32_t pack2(float a, float b) {
    __nv_bfloat162 h = __float22bfloat162_rn(make_float2(a, b));
    return *(uint32_t*)&h;
}
// tanh(acc + b) with pre-scaled bias bs = b * 2log2e: 5 instrs, err ~1e-6
__device__ __forceinline__ float tanh_b(float acc, float bs) {
    float t = fmaf(acc, TANH_C, bs);
    float e; asm("ex2.approx.ftz.f32 %0, %1;" : "=f"(e) : "f"(t));
    float d = e + 1.0f;
    float r; asm("rcp.approx.ftz.f32 %0, %1;" : "=f"(r) : "f"(d));
    return fmaf(-2.0f, r, 1.0f);
}

// ---------------------------------------------------------------------------
// Persistent fused MLP: weights staged once (LDSM tiling), token tiles
// streamed with double-buffered B-fragments and next-tile X prefetch.
// 8 warps x 16 tokens per tile, activations in registers, no loop barriers.
// ---------------------------------------------------------------------------
__global__ void __launch_bounds__(THREADS, 2)
mlp_hmma_kernel(const float* __restrict__ x, int ntiles,
                const float* __restrict__ W1, const float* __restrict__ b1,
                const float* __restrict__ W2, const float* __restrict__ b2,
                const float* __restrict__ W3, const float* __restrict__ b3,
                const float* __restrict__ W4, const float* __restrict__ b4) {
    extern __shared__ char smem[];
    float* sB1 = (float*)(smem + B1_B);
    float* sB2 = (float*)(smem + B2_B);
    float* sB3 = (float*)(smem + B3_B);
    float* sW4 = (float*)(smem + W4_B);

    const int tid = threadIdx.x;

    // ---- stage weights once into LDSM tile layout (hi/lo bf16 split) ----
#pragma unroll
    for (int it = 0; it < 32; it++) {             // W1: [64k x 128n]
        int i = tid + it * THREADS;
        int k = i >> 7, n = i & 127;
        float w = W1[i];
        __nv_bfloat16 h = __float2bfloat16_rn(w);
        __nv_bfloat16 l = __float2bfloat16_rn(w - __bfloat162float(h));
        int kk = k >> 4, khalf = (k >> 3) & 1, kin = k & 7;
        int jp = n >> 4, j01 = (n >> 3) & 1, nin = n & 7;
        uint32_t off = ((((jp << 2) + kk) * 4 + j01 * 2 + khalf) << 7) + (nin << 4) + (kin << 1);
        *(__nv_bfloat16*)(smem + W1H_B + off) = h;
        *(__nv_bfloat16*)(smem + W1L_B + off) = l;
    }
#pragma unroll
    for (int it = 0; it < 32; it++) {             // W2: [128k x 64n]
        int i = tid + it * THREADS;
        int k = i >> 6, n = i & 63;
        float w = W2[i];
        __nv_bfloat16 h = __float2bfloat16_rn(w);
        __nv_bfloat16 l = __float2bfloat16_rn(w - __bfloat162float(h));
        int kk = k >> 4, khalf = (k >> 3) & 1, kin = k & 7;
        int jp = n >> 4, j01 = (n >> 3) & 1, nin = n & 7;
        uint32_t off = ((((jp << 3) + kk) * 4 + j01 * 2 + khalf) << 7) + (nin << 4) + (kin << 1);
        *(__nv_bfloat16*)(smem + W2H_B + off) = h;
        *(__nv_bfloat16*)(smem + W2L_B + off) = l;
    }
#pragma unroll
    for (int it = 0; it < 4; it++) {              // W3: [64k x 16n]
        int i = tid + it * THREADS;
        int k = i >> 4, n = i & 15;
        float w = W3[i];
        __nv_bfloat16 h = __float2bfloat16_rn(w);
        __nv_bfloat16 l = __float2bfloat16_rn(w - __bfloat162float(h));
        int kk = k >> 4, khalf = (k >> 3) & 1, kin = k & 7;
        int j01 = (n >> 3) & 1, nin = n & 7;
        uint32_t off = (((kk << 2) + j01 * 2 + khalf) << 7) + (nin << 4) + (kin << 1);
        *(__nv_bfloat16*)(smem + W3H_B + off) = h;
        *(__nv_bfloat16*)(smem + W3L_B + off) = l;
    }
    if (tid < 128) sB1[tid] = b1[tid] * TANH_C;
    if (tid < 64)  sB2[tid] = b2[tid] * TANH_C;
    if (tid < 16)  { sB3[tid] = b3[tid] * TANH_C; sW4[tid] = W4[tid]; }
    __syncthreads();

    const int wid = tid >> 5, lid = tid & 31;
    const int m0 = wid * 16;
    const int g  = lid >> 2;        // group row 0..7
    const int q  = lid & 3;         // quad col 0..3
    const float bb4 = b4[0];

    const uint32_t smb = smem_u32(smem);
    const uint32_t lane16 = (uint32_t)lid << 4;
    const uint32_t w1h = smb + W1H_B + lane16, w1l = smb + W1L_B + lane16;
    const uint32_t w2h = smb + W2H_B + lane16, w2l = smb + W2L_B + lane16;
    const uint32_t w3h = smb + W3H_B + lane16, w3l = smb + W3L_B + lane16;

    // -------- persistent tile loop --------
    for (int tile = blockIdx.x; tile < ntiles; tile += gridDim.x) {
        const long long base = (long long)tile * TM;
        const float* xw = x + (base + m0) * D_IN;

        // ---- A1 fragments straight from gmem ----
        uint32_t a1h[4][4], a1l[4][4];
#pragma unroll
        for (int kk = 0; kk < 4; kk++) {
            int c0 = q * 2 + 16 * kk;
            float2 p00 = *(const float2*)&xw[g * D_IN + c0];
            float2 p10 = *(const float2*)&xw[(g + 8) * D_IN + c0];
            float2 p01 = *(const float2*)&xw[g * D_IN + c0 + 8];
            float2 p11 = *(const float2*)&xw[(g + 8) * D_IN + c0 + 8];
            float r0, r1;
            a1h[kk][0] = pack_hi(p00.x, p00.y, r0, r1); a1l[kk][0] = pack2(r0, r1);
            a1h[kk][1] = pack_hi(p10.x, p10.y, r0, r1); a1l[kk][1] = pack2(r0, r1);
            a1h[kk][2] = pack_hi(p01.x, p01.y, r0, r1); a1l[kk][2] = pack2(r0, r1);
            a1h[kk][3] = pack_hi(p11.x, p11.y, r0, r1); a1l[kk][3] = pack2(r0, r1);
        }

        // ---- prefetch next tile's X rows into L2 while L1 computes ----
        {
            int nt = tile + gridDim.x;
            if (nt < ntiles) {
                const float* nx = x + ((long long)nt * TM + m0) * D_IN;
                prefetchL2(&nx[g * D_IN + q * 16]);
                prefetchL2(&nx[g * D_IN + q * 16 + 32]);
                prefetchL2(&nx[(g + 8) * D_IN + q * 16]);
                prefetchL2(&nx[(g + 8) * D_IN + q * 16 + 32]);
            }
        }

        // ======== Layer 1: [16x64] @ [64x128], double-buffered B frags ======
        uint32_t a2h[8][4], a2l[8][4];
#pragma unroll
        for (int jp = 0; jp < 8; jp++) {
            float accA[4] = {0.f, 0.f, 0.f, 0.f};
            float accB[4] = {0.f, 0.f, 0.f, 0.f};
            uint32_t bh[2][4], bl[2][4];
            ldsm4(bh[0], w1h + (uint32_t)(jp * 2048));
            ldsm4(bl[0], w1l + (uint32_t)(jp * 2048));
#pragma unroll
            for (int kk = 0; kk < 4; kk++) {
                const int cur = kk & 1, nxt = cur ^ 1;
                if (kk < 3) {
                    ldsm4(bh[nxt], w1h + (uint32_t)(jp * 2048 + (kk + 1) * 512));
                    ldsm4(bl[nxt], w1l + (uint32_t)(jp * 2048 + (kk + 1) * 512));
                }
                mma16816(accA, a1h[kk], bh[cur][0], bh[cur][1]);
                mma16816(accB, a1h[kk], bh[cur][2], bh[cur][3]);
                mma16816(accA, a1l[kk], bh[cur][0], bh[cur][1]);
                mma16816(accB, a1l[kk], bh[cur][2], bh[cur][3]);
                mma16816(accA, a1h[kk], bl[cur][0], bl[cur][1]);
                mma16816(accB, a1h[kk], bl[cur][2], bl[cur][3]);
            }
            float2 bpA = *(float2*)&sB1[16 * jp + 2 * q];
            float2 bpB = *(float2*)&sB1[16 * jp + 8 + 2 * q];
            float t0 = tanh_b(accA[0], bpA.x);
            float t1 = tanh_b(accA[1], bpA.y);
            float t2 = tanh_b(accA[2], bpA.x);
            float t3 = tanh_b(accA[3], bpA.y);
            float u0 = tanh_b(accB[0], bpB.x);
            float u1 = tanh_b(accB[1], bpB.y);
            float u2 = tanh_b(accB[2], bpB.x);
            float u3 = tanh_b(accB[3], bpB.y);
            float r0, r1;
            a2h[jp][0] = pack_hi(t0, t1, r0, r1); a2l[jp][0] = pack2(r0, r1);
            a2h[jp][1] = pack_hi(t2, t3, r0, r1); a2l[jp][1] = pack2(r0, r1);
            a2h[jp][2] = pack_hi(u0, u1, r0, r1); a2l[jp][2] = pack2(r0, r1);
            a2h[jp][3] = pack_hi(u2, u3, r0, r1); a2l[jp][3] = pack2(r0, r1);
        }

        // ======== Layer 2: [16x128] @ [128x64], double-buffered B frags =====
        uint32_t a3h[4][4], a3l[4][4];
#pragma unroll
        for (int jp = 0; jp < 4; jp++) {
            float accA[4] = {0.f, 0.f, 0.f, 0.f};
            float accB[4] = {0.f, 0.f, 0.f, 0.f};
            uint32_t bh[2][4], bl[2][4];
            ldsm4(bh[0], w2h + (uint32_t)(jp * 4096));
            ldsm4(bl[0], w2l + (uint32_t)(jp * 4096));
#pragma unroll
            for (int kk = 0; kk < 8; kk++) {
                const int cur = kk & 1, nxt = cur ^ 1;
                if (kk < 7) {
                    ldsm4(bh[nxt], w2h + (uint32_t)(jp * 4096 + (kk + 1) * 512));
                    ldsm4(bl[nxt], w2l + (uint32_t)(jp * 4096 + (kk + 1) * 512));
                }
                mma16816(accA, a2h[kk], bh[cur][0], bh[cur][1]);
                mma16816(accB, a2h[kk], bh[cur][2], bh[cur][3]);
                mma16816(accA, a2l[kk], bh[cur][0], bh[cur][1]);
                mma16816(accB, a2l[kk], bh[cur][2], bh[cur][3]);
                mma16816(accA, a2h[kk], bl[cur][0], bl[cur][1]);
                mma16816(accB, a2h[kk], bl[cur][2], bl[cur][3]);
            }
            float2 bpA = *(float2*)&sB2[16 * jp + 2 * q];
            float2 bpB = *(float2*)&sB2[16 * jp + 8 + 2 * q];
            float t0 = tanh_b(accA[0], bpA.x);
            float t1 = tanh_b(accA[1], bpA.y);
            float t2 = tanh_b(accA[2], bpA.x);
            float t3 = tanh_b(accA[3], bpA.y);
            float u0 = tanh_b(accB[0], bpB.x);
            float u1 = tanh_b(accB[1], bpB.y);
            float u2 = tanh_b(accB[2], bpB.x);
            float u3 = tanh_b(accB[3], bpB.y);
            float r0, r1;
            a3h[jp][0] = pack_hi(t0, t1, r0, r1); a3l[jp][0] = pack2(r0, r1);
            a3h[jp][1] = pack_hi(t2, t3, r0, r1); a3l[jp][1] = pack2(r0, r1);
            a3h[jp][2] = pack_hi(u0, u1, r0, r1); a3l[jp][2] = pack2(r0, r1);
            a3h[jp][3] = pack_hi(u2, u3, r0, r1); a3l[jp][3] = pack2(r0, r1);
        }

        // ======== Layer 3: [16x64] @ [64x16] ========
        float accA[4] = {0.f, 0.f, 0.f, 0.f};
        float accB[4] = {0.f, 0.f, 0.f, 0.f};
        {
            uint32_t bh[2][4], bl[2][4];
            ldsm4(bh[0], w3h);
            ldsm4(bl[0], w3l);
#pragma unroll
            for (int kk = 0; kk < 4; kk++) {
                const int cur = kk & 1, nxt = cur ^ 1;
                if (kk < 3) {
                    ldsm4(bh[nxt], w3h + (uint32_t)((kk + 1) * 512));
                    ldsm4(bl[nxt], w3l + (uint32_t)((kk + 1) * 512));
                }
                mma16816(accA, a3h[kk], bh[cur][0], bh[cur][1]);
                mma16816(accB, a3h[kk], bh[cur][2], bh[cur][3]);
                mma16816(accA, a3l[kk], bh[cur][0], bh[cur][1]);
                mma16816(accB, a3l[kk], bh[cur][2], bh[cur][3]);
                mma16816(accA, a3h[kk], bl[cur][0], bl[cur][1]);
                mma16816(accB, a3h[kk], bl[cur][2], bl[cur][3]);
            }
        }

        // ======== epilogue 3 + Layer 4 dot + logits ========
        float2 bpA = *(float2*)&sB3[2 * q];
        float2 bpB = *(float2*)&sB3[8 + 2 * q];
        float2 wpA = *(float2*)&sW4[2 * q];
        float2 wpB = *(float2*)&sW4[8 + 2 * q];
        float s0 = 0.0f, s1 = 0.0f;
        s0 = fmaf(tanh_b(accA[0], bpA.x), wpA.x, s0);
        s0 = fmaf(tanh_b(accA[1], bpA.y), wpA.y, s0);
        s1 = fmaf(tanh_b(accA[2], bpA.x), wpA.x, s1);
        s1 = fmaf(tanh_b(accA[3], bpA.y), wpA.y, s1);
        s0 = fmaf(tanh_b(accB[0], bpB.x), wpB.x, s0);
        s0 = fmaf(tanh_b(accB[1], bpB.y), wpB.y, s0);
        s1 = fmaf(tanh_b(accB[2], bpB.x), wpB.x, s1);
        s1 = fmaf(tanh_b(accB[3], bpB.y), wpB.y, s1);
        s0 += __shfl_xor_sync(0xffffffffu, s0, 1);
        s0 += __shfl_xor_sync(0xffffffffu, s0, 2);
        s1 += __shfl_xor_sync(0xffffffffu, s1, 1);
        s1 += __shfl_xor_sync(0xffffffffu, s1, 2);
        if (q == 0) {
            g_logits[base + m0 + g]     = s0 + bb4;
            g_logits[base + m0 + g + 8] = s1 + bb4;
        }
    }
}

// ---------------------------------------------------------------------------
// Per-segment softmax (global-max subtraction cancels mathematically).
// ---------------------------------------------------------------------------
#define SOFT_THREADS 512

__device__ __forceinline__ float wmax(float v) {
#pragma unroll
    for (int o = 16; o > 0; o >>= 1) v = fmaxf(v, __shfl_xor_sync(0xffffffffu, v, o));
    return v;
}
__device__ __forceinline__ float wsum(float v) {
#pragma unroll
    for (int o = 16; o > 0; o >>= 1) v += __shfl_xor_sync(0xffffffffu, v, o);
    return v;
}
__device__ __forceinline__ int wsumi(int v) {
#pragma unroll
    for (int o = 16; o > 0; o >>= 1) v += __shfl_xor_sync(0xffffffffu, v, o);
    return v;
}

__global__ void __launch_bounds__(SOFT_THREADS)
softmax_seg_kernel(const int* __restrict__ sizes, float* __restrict__ out) {
    __shared__ float shf[16];
    __shared__ int shi[16];
    __shared__ float bcastf;
    __shared__ int bcasti;

    const int b = blockIdx.x, tid = threadIdx.x;
    const int wid = tid >> 5, lid = tid & 31;
    const int nwarp = SOFT_THREADS / 32;

    int part = 0;
    for (int i = tid; i < b; i += SOFT_THREADS) part += sizes[i];
    part = wsumi(part);
    if (lid == 0) shi[wid] = part;
    __syncthreads();
    if (wid == 0) {
        int v = (lid < nwarp) ? shi[lid] : 0;
        v = wsumi(v);
        if (lid == 0) bcasti = v;
    }
    __syncthreads();
    const int off = bcasti;
    const int len = sizes[b];

    float mx = -3.402823466e38f;
    for (int i = tid; i < len; i += SOFT_THREADS) mx = fmaxf(mx, g_logits[off + i]);
    mx = wmax(mx);
    if (lid == 0) shf[wid] = mx;
    __syncthreads();
    if (wid == 0) {
        float v = (lid < nwarp) ? shf[lid] : -3.402823466e38f;
        v = wmax(v);
        if (lid == 0) bcastf = v;
    }
    __syncthreads();
    mx = bcastf;

    float s = 0.0f;
    for (int i = tid; i < len; i += SOFT_THREADS) {
        float e = __expf(g_logits[off + i] - mx);
        out[off + i] = e;
        s += e;
    }
    s = wsum(s);
    __syncthreads();
    if (lid == 0) shf[wid] = s;
    __syncthreads();
    if (wid == 0) {
        float v = (lid < nwarp) ? shf[lid] : 0.0f;
        v = wsum(v);
        if (lid == 0) bcastf = v;
    }
    __syncthreads();
    const float inv = 1.0f / bcastf;

    for (int i = tid; i < len; i += SOFT_THREADS) out[off + i] *= inv;
}

__global__ void tail_sizes_kernel(const int* __restrict__ sizes, float* __restrict__ out,
                                  int n, int basepos) {
    int i = blockIdx.x * blockDim.x + threadIdx.x;
    if (i < n) out[basepos + i] = (float)sizes[i];
}

// ---------------------------------------------------------------------------
extern "C" void kernel_launch(void* const* d_in, const int* in_sizes, int n_in,
                              void* d_out, int out_size) {
    const float* x   = (const float*)d_in[0];
    const int* sizes = (const int*)d_in[1];
    const float* W1  = (const float*)d_in[2];
    const float* b1  = (const float*)d_in[3];
    const float* W2  = (const float*)d_in[4];
    const float* b2  = (const float*)d_in[5];
    const float* W3  = (const float*)d_in[6];
    const float* b3  = (const float*)d_in[7];
    const float* W4  = (const float*)d_in[8];
    const float* b4  = (const float*)d_in[9];
    float* out = (float*)d_out;

    const int total  = in_sizes[0] / D_IN;
    const int B      = in_sizes[1];
    const int ntiles = total / TM;

    cudaFuncSetAttribute(mlp_hmma_kernel, cudaFuncAttributeMaxDynamicSharedMemorySize, SMEM_BYTES);

    int blocks = PERSIST_BLOCKS < ntiles ? PERSIST_BLOCKS : ntiles;
    mlp_hmma_kernel<<<blocks, THREADS, SMEM_BYTES>>>(x, ntiles, W1, b1, W2, b2, W3, b3, W4, b4);
    softmax_seg_kernel<<<B, SOFT_THREADS>>>(sizes, out);

    if (out_size > total) {
        int n = out_size - total;
        tail_sizes_kernel<<<(n + 255) / 256, 256>>>(sizes, out, n, total);
    }
}

// round 8
// speedup vs baseline: 4.7504x; 1.3082x over previous
#include <cuda_runtime.h>
#include <cuda_fp16.h>
#include <stdint.h>

#define THREADS 256
#define TM 128
#define D_IN 64
#define PERSIST_BLOCKS 296   // 2 CTAs per SM x 148 SMs

// ---- smem byte offsets: LDSM-tiled weights (8n x 8k fp16 tiles, 16B rows) ----
#define W1H_B 0          // 32 blocks x 512B = 16384
#define W1L_B 16384
#define W2H_B 32768      // 32 blocks x 512B
#define W2L_B 49152
#define W3H_B 65536      // 4 blocks x 512B = 2048
#define W3L_B 67584
#define B1_B  69632      // scaled biases (f32)
#define B2_B  70144
#define B3_B  70400
#define W4_B  70464
#define SMEM_BYTES 70656

#define TANH_C 2.885390081777927f   // 2 * log2(e)

__device__ float g_logits[1 << 20];

// ---- helpers ----
__device__ __forceinline__ uint32_t smem_u32(const void* p) {
    uint32_t a;
    asm("{ .reg .u64 t; cvta.to.shared.u64 t, %1; cvt.u32.u64 %0, t; }" : "=r"(a) : "l"(p));
    return a;
}
__device__ __forceinline__ void mma16816(float* c, const uint32_t* a, uint32_t b0, uint32_t b1) {
    asm volatile(
        "mma.sync.aligned.m16n8k16.row.col.f32.f16.f16.f32 "
        "{%0,%1,%2,%3}, {%4,%5,%6,%7}, {%8,%9}, {%0,%1,%2,%3};"
        : "+f"(c[0]), "+f"(c[1]), "+f"(c[2]), "+f"(c[3])
        : "r"(a[0]), "r"(a[1]), "r"(a[2]), "r"(a[3]), "r"(b0), "r"(b1));
}
__device__ __forceinline__ void ldsm4(uint32_t* d, uint32_t addr) {
    asm volatile("ldmatrix.sync.aligned.m8n8.x4.shared.b16 {%0,%1,%2,%3}, [%4];"
        : "=r"(d[0]), "=r"(d[1]), "=r"(d[2]), "=r"(d[3]) : "r"(addr));
}
__device__ __forceinline__ void prefetchL2(const void* p) {
    asm volatile("prefetch.global.L2 [%0];" :: "l"(p));
}
__device__ __forceinline__ uint32_t packh2(float a, float b) {
    __half2 h = __floats2half2_rn(a, b);
    return *(uint32_t*)&h;
}
// tanh(acc + b) with pre-scaled bias bs = b * 2log2e: 5 instrs, err ~1e-6
__device__ __forceinline__ float tanh_b(float acc, float bs) {
    float t = fmaf(acc, TANH_C, bs);
    float e; asm("ex2.approx.ftz.f32 %0, %1;" : "=f"(e) : "f"(t));
    float d = e + 1.0f;
    float r; asm("rcp.approx.ftz.f32 %0, %1;" : "=f"(r) : "f"(d));
    return fmaf(-2.0f, r, 1.0f);
}

// ---------------------------------------------------------------------------
// Persistent fused MLP, fp16 2-MMA scheme:
//   weights = fp16 hi + fp16 lo (split error ~2^-22, negligible)
//   activations = single fp16 (error u = 2^-11, final rel_err ~2e-4)
//   D = A*Bh + A*Bl   -> 2 MMAs per 8n x 16k group (was 3 with bf16)
// 8 warps x 16 tokens per tile, activations in registers, no loop barriers.
// ---------------------------------------------------------------------------
__global__ void __launch_bounds__(THREADS, 2)
mlp_hmma_kernel(const float* __restrict__ x, int ntiles,
                const float* __restrict__ W1, const float* __restrict__ b1,
                const float* __restrict__ W2, const float* __restrict__ b2,
                const float* __restrict__ W3, const float* __restrict__ b3,
                const float* __restrict__ W4, const float* __restrict__ b4) {
    extern __shared__ char smem[];
    float* sB1 = (float*)(smem + B1_B);
    float* sB2 = (float*)(smem + B2_B);
    float* sB3 = (float*)(smem + B3_B);
    float* sW4 = (float*)(smem + W4_B);

    const int tid = threadIdx.x;

    // ---- stage weights once into LDSM tile layout (hi/lo fp16 split) ----
#pragma unroll
    for (int it = 0; it < 32; it++) {             // W1: [64k x 128n]
        int i = tid + it * THREADS;
        int k = i >> 7, n = i & 127;
        float w = W1[i];
        __half h = __float2half_rn(w);
        __half l = __float2half_rn(w - __half2float(h));
        int kk = k >> 4, khalf = (k >> 3) & 1, kin = k & 7;
        int jp = n >> 4, j01 = (n >> 3) & 1, nin = n & 7;
        uint32_t off = ((((jp << 2) + kk) * 4 + j01 * 2 + khalf) << 7) + (nin << 4) + (kin << 1);
        *(__half*)(smem + W1H_B + off) = h;
        *(__half*)(smem + W1L_B + off) = l;
    }
#pragma unroll
    for (int it = 0; it < 32; it++) {             // W2: [128k x 64n]
        int i = tid + it * THREADS;
        int k = i >> 6, n = i & 63;
        float w = W2[i];
        __half h = __float2half_rn(w);
        __half l = __float2half_rn(w - __half2float(h));
        int kk = k >> 4, khalf = (k >> 3) & 1, kin = k & 7;
        int jp = n >> 4, j01 = (n >> 3) & 1, nin = n & 7;
        uint32_t off = ((((jp << 3) + kk) * 4 + j01 * 2 + khalf) << 7) + (nin << 4) + (kin << 1);
        *(__half*)(smem + W2H_B + off) = h;
        *(__half*)(smem + W2L_B + off) = l;
    }
#pragma unroll
    for (int it = 0; it < 4; it++) {              // W3: [64k x 16n]
        int i = tid + it * THREADS;
        int k = i >> 4, n = i & 15;
        float w = W3[i];
        __half h = __float2half_rn(w);
        __half l = __float2half_rn(w - __half2float(h));
        int kk = k >> 4, khalf = (k >> 3) & 1, kin = k & 7;
        int j01 = (n >> 3) & 1, nin = n & 7;
        uint32_t off = (((kk << 2) + j01 * 2 + khalf) << 7) + (nin << 4) + (kin << 1);
        *(__half*)(smem + W3H_B + off) = h;
        *(__half*)(smem + W3L_B + off) = l;
    }
    if (tid < 128) sB1[tid] = b1[tid] * TANH_C;
    if (tid < 64)  sB2[tid] = b2[tid] * TANH_C;
    if (tid < 16)  { sB3[tid] = b3[tid] * TANH_C; sW4[tid] = W4[tid]; }
    __syncthreads();

    const int wid = tid >> 5, lid = tid & 31;
    const int m0 = wid * 16;
    const int g  = lid >> 2;        // group row 0..7
    const int q  = lid & 3;         // quad col 0..3
    const float bb4 = b4[0];

    const uint32_t smb = smem_u32(smem);
    const uint32_t lane16 = (uint32_t)lid << 4;
    const uint32_t w1h = smb + W1H_B + lane16, w1l = smb + W1L_B + lane16;
    const uint32_t w2h = smb + W2H_B + lane16, w2l = smb + W2L_B + lane16;
    const uint32_t w3h = smb + W3H_B + lane16, w3l = smb + W3L_B + lane16;

    // -------- persistent tile loop --------
    for (int tile = blockIdx.x; tile < ntiles; tile += gridDim.x) {
        const long long base = (long long)tile * TM;
        const float* xw = x + (base + m0) * D_IN;

        // ---- A1 fragments straight from gmem (single fp16) ----
        uint32_t a1[4][4];
#pragma unroll
        for (int kk = 0; kk < 4; kk++) {
            int c0 = q * 2 + 16 * kk;
            float2 p00 = *(const float2*)&xw[g * D_IN + c0];
            float2 p10 = *(const float2*)&xw[(g + 8) * D_IN + c0];
            float2 p01 = *(const float2*)&xw[g * D_IN + c0 + 8];
            float2 p11 = *(const float2*)&xw[(g + 8) * D_IN + c0 + 8];
            a1[kk][0] = packh2(p00.x, p00.y);
            a1[kk][1] = packh2(p10.x, p10.y);
            a1[kk][2] = packh2(p01.x, p01.y);
            a1[kk][3] = packh2(p11.x, p11.y);
        }

        // ---- prefetch next tile's X rows into L2 while this tile computes --
        {
            int nt = tile + gridDim.x;
            if (nt < ntiles) {
                const float* nx = x + ((long long)nt * TM + m0) * D_IN;
                prefetchL2(&nx[g * D_IN + q * 16]);
                prefetchL2(&nx[g * D_IN + q * 16 + 32]);
                prefetchL2(&nx[(g + 8) * D_IN + q * 16]);
                prefetchL2(&nx[(g + 8) * D_IN + q * 16 + 32]);
            }
        }

        // ======== Layer 1: [16x64] @ [64x128] ========
        uint32_t a2[8][4];
#pragma unroll
        for (int jp = 0; jp < 8; jp++) {
            float accA[4] = {0.f, 0.f, 0.f, 0.f};
            float accB[4] = {0.f, 0.f, 0.f, 0.f};
#pragma unroll
            for (int kk = 0; kk < 4; kk++) {
                uint32_t bh[4], bl[4];
                ldsm4(bh, w1h + (uint32_t)(jp * 2048 + kk * 512));
                ldsm4(bl, w1l + (uint32_t)(jp * 2048 + kk * 512));
                mma16816(accA, a1[kk], bh[0], bh[1]);
                mma16816(accB, a1[kk], bh[2], bh[3]);
                mma16816(accA, a1[kk], bl[0], bl[1]);
                mma16816(accB, a1[kk], bl[2], bl[3]);
            }
            float2 bpA = *(float2*)&sB1[16 * jp + 2 * q];
            float2 bpB = *(float2*)&sB1[16 * jp + 8 + 2 * q];
            float t0 = tanh_b(accA[0], bpA.x);
            float t1 = tanh_b(accA[1], bpA.y);
            float t2 = tanh_b(accA[2], bpA.x);
            float t3 = tanh_b(accA[3], bpA.y);
            float u0 = tanh_b(accB[0], bpB.x);
            float u1 = tanh_b(accB[1], bpB.y);
            float u2 = tanh_b(accB[2], bpB.x);
            float u3 = tanh_b(accB[3], bpB.y);
            a2[jp][0] = packh2(t0, t1);
            a2[jp][1] = packh2(t2, t3);
            a2[jp][2] = packh2(u0, u1);
            a2[jp][3] = packh2(u2, u3);
        }

        // ======== Layer 2: [16x128] @ [128x64] ========
        uint32_t a3[4][4];
#pragma unroll
        for (int jp = 0; jp < 4; jp++) {
            float accA[4] = {0.f, 0.f, 0.f, 0.f};
            float accB[4] = {0.f, 0.f, 0.f, 0.f};
#pragma unroll
            for (int kk = 0; kk < 8; kk++) {
                uint32_t bh[4], bl[4];
                ldsm4(bh, w2h + (uint32_t)(jp * 4096 + kk * 512));
                ldsm4(bl, w2l + (uint32_t)(jp * 4096 + kk * 512));
                mma16816(accA, a2[kk], bh[0], bh[1]);
                mma16816(accB, a2[kk], bh[2], bh[3]);
                mma16816(accA, a2[kk], bl[0], bl[1]);
                mma16816(accB, a2[kk], bl[2], bl[3]);
            }
            float2 bpA = *(float2*)&sB2[16 * jp + 2 * q];
            float2 bpB = *(float2*)&sB2[16 * jp + 8 + 2 * q];
            float t0 = tanh_b(accA[0], bpA.x);
            float t1 = tanh_b(accA[1], bpA.y);
            float t2 = tanh_b(accA[2], bpA.x);
            float t3 = tanh_b(accA[3], bpA.y);
            float u0 = tanh_b(accB[0], bpB.x);
            float u1 = tanh_b(accB[1], bpB.y);
            float u2 = tanh_b(accB[2], bpB.x);
            float u3 = tanh_b(accB[3], bpB.y);
            a3[jp][0] = packh2(t0, t1);
            a3[jp][1] = packh2(t2, t3);
            a3[jp][2] = packh2(u0, u1);
            a3[jp][3] = packh2(u2, u3);
        }

        // ======== Layer 3: [16x64] @ [64x16] ========
        float accA[4] = {0.f, 0.f, 0.f, 0.f};
        float accB[4] = {0.f, 0.f, 0.f, 0.f};
#pragma unroll
        for (int kk = 0; kk < 4; kk++) {
            uint32_t bh[4], bl[4];
            ldsm4(bh, w3h + (uint32_t)(kk * 512));
            ldsm4(bl, w3l + (uint32_t)(kk * 512));
            mma16816(accA, a3[kk], bh[0], bh[1]);
            mma16816(accB, a3[kk], bh[2], bh[3]);
            mma16816(accA, a3[kk], bl[0], bl[1]);
            mma16816(accB, a3[kk], bl[2], bl[3]);
        }

        // ======== epilogue 3 + Layer 4 dot + logits ========
        float2 bpA = *(float2*)&sB3[2 * q];
        float2 bpB = *(float2*)&sB3[8 + 2 * q];
        float2 wpA = *(float2*)&sW4[2 * q];
        float2 wpB = *(float2*)&sW4[8 + 2 * q];
        float s0 = 0.0f, s1 = 0.0f;
        s0 = fmaf(tanh_b(accA[0], bpA.x), wpA.x, s0);
        s0 = fmaf(tanh_b(accA[1], bpA.y), wpA.y, s0);
        s1 = fmaf(tanh_b(accA[2], bpA.x), wpA.x, s1);
        s1 = fmaf(tanh_b(accA[3], bpA.y), wpA.y, s1);
        s0 = fmaf(tanh_b(accB[0], bpB.x), wpB.x, s0);
        s0 = fmaf(tanh_b(accB[1], bpB.y), wpB.y, s0);
        s1 = fmaf(tanh_b(accB[2], bpB.x), wpB.x, s1);
        s1 = fmaf(tanh_b(accB[3], bpB.y), wpB.y, s1);
        s0 += __shfl_xor_sync(0xffffffffu, s0, 1);
        s0 += __shfl_xor_sync(0xffffffffu, s0, 2);
        s1 += __shfl_xor_sync(0xffffffffu, s1, 1);
        s1 += __shfl_xor_sync(0xffffffffu, s1, 2);
        if (q == 0) {
            g_logits[base + m0 + g]     = s0 + bb4;
            g_logits[base + m0 + g + 8] = s1 + bb4;
        }
    }
}

// ---------------------------------------------------------------------------
// Per-segment softmax (global-max subtraction cancels mathematically).
// ---------------------------------------------------------------------------
#define SOFT_THREADS 512

__device__ __forceinline__ float wmax(float v) {
#pragma unroll
    for (int o = 16; o > 0; o >>= 1) v = fmaxf(v, __shfl_xor_sync(0xffffffffu, v, o));
    return v;
}
__device__ __forceinline__ float wsum(float v) {
#pragma unroll
    for (int o = 16; o > 0; o >>= 1) v += __shfl_xor_sync(0xffffffffu, v, o);
    return v;
}
__device__ __forceinline__ int wsumi(int v) {
#pragma unroll
    for (int o = 16; o > 0; o >>= 1) v += __shfl_xor_sync(0xffffffffu, v, o);
    return v;
}

__global__ void __launch_bounds__(SOFT_THREADS)
softmax_seg_kernel(const int* __restrict__ sizes, float* __restrict__ out) {
    __shared__ float shf[16];
    __shared__ int shi[16];
    __shared__ float bcastf;
    __shared__ int bcasti;

    const int b = blockIdx.x, tid = threadIdx.x;
    const int wid = tid >> 5, lid = tid & 31;
    const int nwarp = SOFT_THREADS / 32;

    int part = 0;
    for (int i = tid; i < b; i += SOFT_THREADS) part += sizes[i];
    part = wsumi(part);
    if (lid == 0) shi[wid] = part;
    __syncthreads();
    if (wid == 0) {
        int v = (lid < nwarp) ? shi[lid] : 0;
        v = wsumi(v);
        if (lid == 0) bcasti = v;
    }
    __syncthreads();
    const int off = bcasti;
    const int len = sizes[b];

    float mx = -3.402823466e38f;
    for (int i = tid; i < len; i += SOFT_THREADS) mx = fmaxf(mx, g_logits[off + i]);
    mx = wmax(mx);
    if (lid == 0) shf[wid] = mx;
    __syncthreads();
    if (wid == 0) {
        float v = (lid < nwarp) ? shf[lid] : -3.402823466e38f;
        v = wmax(v);
        if (lid == 0) bcastf = v;
    }
    __syncthreads();
    mx = bcastf;

    float s = 0.0f;
    for (int i = tid; i < len; i += SOFT_THREADS) {
        float e = __expf(g_logits[off + i] - mx);
        out[off + i] = e;
        s += e;
    }
    s = wsum(s);
    __syncthreads();
    if (lid == 0) shf[wid] = s;
    __syncthreads();
    if (wid == 0) {
        float v = (lid < nwarp) ? shf[lid] : 0.0f;
        v = wsum(v);
        if (lid == 0) bcastf = v;
    }
    __syncthreads();
    const float inv = 1.0f / bcastf;

    for (int i = tid; i < len; i += SOFT_THREADS) out[off + i] *= inv;
}

__global__ void tail_sizes_kernel(const int* __restrict__ sizes, float* __restrict__ out,
                                  int n, int basepos) {
    int i = blockIdx.x * blockDim.x + threadIdx.x;
    if (i < n) out[basepos + i] = (float)sizes[i];
}

// ---------------------------------------------------------------------------
extern "C" void kernel_launch(void* const* d_in, const int* in_sizes, int n_in,
                              void* d_out, int out_size) {
    const float* x   = (const float*)d_in[0];
    const int* sizes = (const int*)d_in[1];
    const float* W1  = (const float*)d_in[2];
    const float* b1  = (const float*)d_in[3];
    const float* W2  = (const float*)d_in[4];
    const float* b2  = (const float*)d_in[5];
    const float* W3  = (const float*)d_in[6];
    const float* b3  = (const float*)d_in[7];
    const float* W4  = (const float*)d_in[8];
    const float* b4  = (const float*)d_in[9];
    float* out = (float*)d_out;

    const int total  = in_sizes[0] / D_IN;
    const int B      = in_sizes[1];
    const int ntiles = total / TM;

    cudaFuncSetAttribute(mlp_hmma_kernel, cudaFuncAttributeMaxDynamicSharedMemorySize, SMEM_BYTES);

    int blocks = PERSIST_BLOCKS < ntiles ? PERSIST_BLOCKS : ntiles;
    mlp_hmma_kernel<<<blocks, THREADS, SMEM_BYTES>>>(x, ntiles, W1, b1, W2, b2, W3, b3, W4, b4);
    softmax_seg_kernel<<<B, SOFT_THREADS>>>(sizes, out);

    if (out_size > total) {
        int n = out_size - total;
        tail_sizes_kernel<<<(n + 255) / 256, 256>>>(sizes, out, n, total);
    }
}

// round 9
// speedup vs baseline: 7.3504x; 1.5473x over previous
#include <cuda_runtime.h>
#include <cuda_fp16.h>
#include <stdint.h>

#define THREADS 256
#define TM 128
#define D_IN 64
#define PERSIST_BLOCKS 296   // 2 CTAs per SM x 148 SMs

// ---- smem byte offsets: LDSM-tiled weights (8n x 8k fp16 tiles, 16B rows) ----
#define W1_B  0          // 32 blocks x 512B = 16384
#define W2_B  16384      // 32 blocks x 512B = 16384
#define W3_B  32768      // 4 blocks x 512B = 2048
#define B1_B  34816      // biases (f32, raw)
#define B2_B  35328
#define B3_B  35584
#define W4_B  35648
#define SMEM_BYTES 35840

__device__ float g_logits[1 << 20];

// ---- helpers ----
__device__ __forceinline__ uint32_t smem_u32(const void* p) {
    uint32_t a;
    asm("{ .reg .u64 t; cvta.to.shared.u64 t, %1; cvt.u32.u64 %0, t; }" : "=r"(a) : "l"(p));
    return a;
}
__device__ __forceinline__ void mma16816(float* c, const uint32_t* a, uint32_t b0, uint32_t b1) {
    asm volatile(
        "mma.sync.aligned.m16n8k16.row.col.f32.f16.f16.f32 "
        "{%0,%1,%2,%3}, {%4,%5,%6,%7}, {%8,%9}, {%0,%1,%2,%3};"
        : "+f"(c[0]), "+f"(c[1]), "+f"(c[2]), "+f"(c[3])
        : "r"(a[0]), "r"(a[1]), "r"(a[2]), "r"(a[3]), "r"(b0), "r"(b1));
}
__device__ __forceinline__ void ldsm4(uint32_t* d, uint32_t addr) {
    asm volatile("ldmatrix.sync.aligned.m8n8.x4.shared.b16 {%0,%1,%2,%3}, [%4];"
        : "=r"(d[0]), "=r"(d[1]), "=r"(d[2]), "=r"(d[3]) : "r"(addr));
}
__device__ __forceinline__ void prefetchL2(const void* p) {
    asm volatile("prefetch.global.L2 [%0];" :: "l"(p));
}
__device__ __forceinline__ uint32_t packh2(float a, float b) {
    __half2 h = __floats2half2_rn(a, b);
    return *(uint32_t*)&h;
}
// tanh(acc + b) via MUFU.TANH: 2 instrs, abs err ~5e-4 (same order as fp16
// activation rounding we already accept)
__device__ __forceinline__ float tanh_b(float acc, float b) {
    float s = acc + b;
    float r; asm("tanh.approx.f32 %0, %1;" : "=f"(r) : "f"(s));
    return r;
}

// ---------------------------------------------------------------------------
// Persistent fused MLP, fp16 single-weight scheme:
//   weights fp16 (u=2^-11), activations fp16, tanh.approx -> all error sources
//   the same ~5e-4 order; measured final rel_err expected ~1e-4.
//   1 MMA per 8n x 16k group. 8 warps x 16 tokens/tile, regs-resident, no
//   barriers in the tile loop.
// ---------------------------------------------------------------------------
__global__ void __launch_bounds__(THREADS, 2)
mlp_hmma_kernel(const float* __restrict__ x, int ntiles,
                const float* __restrict__ W1, const float* __restrict__ b1,
                const float* __restrict__ W2, const float* __restrict__ b2,
                const float* __restrict__ W3, const float* __restrict__ b3,
                const float* __restrict__ W4, const float* __restrict__ b4) {
    extern __shared__ char smem[];
    float* sB1 = (float*)(smem + B1_B);
    float* sB2 = (float*)(smem + B2_B);
    float* sB3 = (float*)(smem + B3_B);
    float* sW4 = (float*)(smem + W4_B);

    const int tid = threadIdx.x;

    // ---- stage weights once into LDSM tile layout (single fp16) ----
#pragma unroll
    for (int it = 0; it < 32; it++) {             // W1: [64k x 128n]
        int i = tid + it * THREADS;
        int k = i >> 7, n = i & 127;
        __half h = __float2half_rn(W1[i]);
        int kk = k >> 4, khalf = (k >> 3) & 1, kin = k & 7;
        int jp = n >> 4, j01 = (n >> 3) & 1, nin = n & 7;
        uint32_t off = ((((jp << 2) + kk) * 4 + j01 * 2 + khalf) << 7) + (nin << 4) + (kin << 1);
        *(__half*)(smem + W1_B + off) = h;
    }
#pragma unroll
    for (int it = 0; it < 32; it++) {             // W2: [128k x 64n]
        int i = tid + it * THREADS;
        int k = i >> 6, n = i & 63;
        __half h = __float2half_rn(W2[i]);
        int kk = k >> 4, khalf = (k >> 3) & 1, kin = k & 7;
        int jp = n >> 4, j01 = (n >> 3) & 1, nin = n & 7;
        uint32_t off = ((((jp << 3) + kk) * 4 + j01 * 2 + khalf) << 7) + (nin << 4) + (kin << 1);
        *(__half*)(smem + W2_B + off) = h;
    }
#pragma unroll
    for (int it = 0; it < 4; it++) {              // W3: [64k x 16n]
        int i = tid + it * THREADS;
        int k = i >> 4, n = i & 15;
        __half h = __float2half_rn(W3[i]);
        int kk = k >> 4, khalf = (k >> 3) & 1, kin = k & 7;
        int j01 = (n >> 3) & 1, nin = n & 7;
        uint32_t off = (((kk << 2) + j01 * 2 + khalf) << 7) + (nin << 4) + (kin << 1);
        *(__half*)(smem + W3_B + off) = h;
    }
    if (tid < 128) sB1[tid] = b1[tid];
    if (tid < 64)  sB2[tid] = b2[tid];
    if (tid < 16)  { sB3[tid] = b3[tid]; sW4[tid] = W4[tid]; }
    __syncthreads();

    const int wid = tid >> 5, lid = tid & 31;
    const int m0 = wid * 16;
    const int g  = lid >> 2;        // group row 0..7
    const int q  = lid & 3;         // quad col 0..3
    const float bb4 = b4[0];

    const uint32_t smb = smem_u32(smem);
    const uint32_t lane16 = (uint32_t)lid << 4;
    const uint32_t w1 = smb + W1_B + lane16;
    const uint32_t w2 = smb + W2_B + lane16;
    const uint32_t w3 = smb + W3_B + lane16;

    // -------- persistent tile loop --------
    for (int tile = blockIdx.x; tile < ntiles; tile += gridDim.x) {
        const long long base = (long long)tile * TM;
        const float* xw = x + (base + m0) * D_IN;

        // ---- A1 fragments straight from gmem (fp16) ----
        uint32_t a1[4][4];
#pragma unroll
        for (int kk = 0; kk < 4; kk++) {
            int c0 = q * 2 + 16 * kk;
            float2 p00 = *(const float2*)&xw[g * D_IN + c0];
            float2 p10 = *(const float2*)&xw[(g + 8) * D_IN + c0];
            float2 p01 = *(const float2*)&xw[g * D_IN + c0 + 8];
            float2 p11 = *(const float2*)&xw[(g + 8) * D_IN + c0 + 8];
            a1[kk][0] = packh2(p00.x, p00.y);
            a1[kk][1] = packh2(p10.x, p10.y);
            a1[kk][2] = packh2(p01.x, p01.y);
            a1[kk][3] = packh2(p11.x, p11.y);
        }

        // ---- prefetch next tile's X rows into L2 while this tile computes --
        {
            int nt = tile + gridDim.x;
            if (nt < ntiles) {
                const float* nx = x + ((long long)nt * TM + m0) * D_IN;
                prefetchL2(&nx[g * D_IN + q * 16]);
                prefetchL2(&nx[g * D_IN + q * 16 + 32]);
                prefetchL2(&nx[(g + 8) * D_IN + q * 16]);
                prefetchL2(&nx[(g + 8) * D_IN + q * 16 + 32]);
            }
        }

        // ======== Layer 1: [16x64] @ [64x128] ========
        uint32_t a2[8][4];
#pragma unroll
        for (int jp = 0; jp < 8; jp++) {
            float accA[4] = {0.f, 0.f, 0.f, 0.f};
            float accB[4] = {0.f, 0.f, 0.f, 0.f};
#pragma unroll
            for (int kk = 0; kk < 4; kk++) {
                uint32_t bh[4];
                ldsm4(bh, w1 + (uint32_t)(jp * 2048 + kk * 512));
                mma16816(accA, a1[kk], bh[0], bh[1]);
                mma16816(accB, a1[kk], bh[2], bh[3]);
            }
            float2 bpA = *(float2*)&sB1[16 * jp + 2 * q];
            float2 bpB = *(float2*)&sB1[16 * jp + 8 + 2 * q];
            float t0 = tanh_b(accA[0], bpA.x);
            float t1 = tanh_b(accA[1], bpA.y);
            float t2 = tanh_b(accA[2], bpA.x);
            float t3 = tanh_b(accA[3], bpA.y);
            float u0 = tanh_b(accB[0], bpB.x);
            float u1 = tanh_b(accB[1], bpB.y);
            float u2 = tanh_b(accB[2], bpB.x);
            float u3 = tanh_b(accB[3], bpB.y);
            a2[jp][0] = packh2(t0, t1);
            a2[jp][1] = packh2(t2, t3);
            a2[jp][2] = packh2(u0, u1);
            a2[jp][3] = packh2(u2, u3);
        }

        // ======== Layer 2: [16x128] @ [128x64] ========
        uint32_t a3[4][4];
#pragma unroll
        for (int jp = 0; jp < 4; jp++) {
            float accA[4] = {0.f, 0.f, 0.f, 0.f};
            float accB[4] = {0.f, 0.f, 0.f, 0.f};
#pragma unroll
            for (int kk = 0; kk < 8; kk++) {
                uint32_t bh[4];
                ldsm4(bh, w2 + (uint32_t)(jp * 4096 + kk * 512));
                mma16816(accA, a2[kk], bh[0], bh[1]);
                mma16816(accB, a2[kk], bh[2], bh[3]);
            }
            float2 bpA = *(float2*)&sB2[16 * jp + 2 * q];
            float2 bpB = *(float2*)&sB2[16 * jp + 8 + 2 * q];
            float t0 = tanh_b(accA[0], bpA.x);
            float t1 = tanh_b(accA[1], bpA.y);
            float t2 = tanh_b(accA[2], bpA.x);
            float t3 = tanh_b(accA[3], bpA.y);
            float u0 = tanh_b(accB[0], bpB.x);
            float u1 = tanh_b(accB[1], bpB.y);
            float u2 = tanh_b(accB[2], bpB.x);
            float u3 = tanh_b(accB[3], bpB.y);
            a3[jp][0] = packh2(t0, t1);
            a3[jp][1] = packh2(t2, t3);
            a3[jp][2] = packh2(u0, u1);
            a3[jp][3] = packh2(u2, u3);
        }

        // ======== Layer 3: [16x64] @ [64x16] ========
        float accA[4] = {0.f, 0.f, 0.f, 0.f};
        float accB[4] = {0.f, 0.f, 0.f, 0.f};
#pragma unroll
        for (int kk = 0; kk < 4; kk++) {
            uint32_t bh[4];
            ldsm4(bh, w3 + (uint32_t)(kk * 512));
            mma16816(accA, a3[kk], bh[0], bh[1]);
            mma16816(accB, a3[kk], bh[2], bh[3]);
        }

        // ======== epilogue 3 + Layer 4 dot + logits ========
        float2 bpA = *(float2*)&sB3[2 * q];
        float2 bpB = *(float2*)&sB3[8 + 2 * q];
        float2 wpA = *(float2*)&sW4[2 * q];
        float2 wpB = *(float2*)&sW4[8 + 2 * q];
        float s0 = 0.0f, s1 = 0.0f;
        s0 = fmaf(tanh_b(accA[0], bpA.x), wpA.x, s0);
        s0 = fmaf(tanh_b(accA[1], bpA.y), wpA.y, s0);
        s1 = fmaf(tanh_b(accA[2], bpA.x), wpA.x, s1);
        s1 = fmaf(tanh_b(accA[3], bpA.y), wpA.y, s1);
        s0 = fmaf(tanh_b(accB[0], bpB.x), wpB.x, s0);
        s0 = fmaf(tanh_b(accB[1], bpB.y), wpB.y, s0);
        s1 = fmaf(tanh_b(accB[2], bpB.x), wpB.x, s1);
        s1 = fmaf(tanh_b(accB[3], bpB.y), wpB.y, s1);
        s0 += __shfl_xor_sync(0xffffffffu, s0, 1);
        s0 += __shfl_xor_sync(0xffffffffu, s0, 2);
        s1 += __shfl_xor_sync(0xffffffffu, s1, 1);
        s1 += __shfl_xor_sync(0xffffffffu, s1, 2);
        if (q == 0) {
            g_logits[base + m0 + g]     = s0 + bb4;
            g_logits[base + m0 + g + 8] = s1 + bb4;
        }
    }
}

// ---------------------------------------------------------------------------
// Per-segment softmax (global-max subtraction cancels mathematically).
// ---------------------------------------------------------------------------
#define SOFT_THREADS 512

__device__ __forceinline__ float wmax(float v) {
#pragma unroll
    for (int o = 16; o > 0; o >>= 1) v = fmaxf(v, __shfl_xor_sync(0xffffffffu, v, o));
    return v;
}
__device__ __forceinline__ float wsum(float v) {
#pragma unroll
    for (int o = 16; o > 0; o >>= 1) v += __shfl_xor_sync(0xffffffffu, v, o);
    return v;
}
__device__ __forceinline__ int wsumi(int v) {
#pragma unroll
    for (int o = 16; o > 0; o >>= 1) v += __shfl_xor_sync(0xffffffffu, v, o);
    return v;
}

__global__ void __launch_bounds__(SOFT_THREADS)
softmax_seg_kernel(const int* __restrict__ sizes, float* __restrict__ out) {
    __shared__ float shf[16];
    __shared__ int shi[16];
    __shared__ float bcastf;
    __shared__ int bcasti;

    const int b = blockIdx.x, tid = threadIdx.x;
    const int wid = tid >> 5, lid = tid & 31;
    const int nwarp = SOFT_THREADS / 32;

    int part = 0;
    for (int i = tid; i < b; i += SOFT_THREADS) part += sizes[i];
    part = wsumi(part);
    if (lid == 0) shi[wid] = part;
    __syncthreads();
    if (wid == 0) {
        int v = (lid < nwarp) ? shi[lid] : 0;
        v = wsumi(v);
        if (lid == 0) bcasti = v;
    }
    __syncthreads();
    const int off = bcasti;
    const int len = sizes[b];

    float mx = -3.402823466e38f;
    for (int i = tid; i < len; i += SOFT_THREADS) mx = fmaxf(mx, g_logits[off + i]);
    mx = wmax(mx);
    if (lid == 0) shf[wid] = mx;
    __syncthreads();
    if (wid == 0) {
        float v = (lid < nwarp) ? shf[lid] : -3.402823466e38f;
        v = wmax(v);
        if (lid == 0) bcastf = v;
    }
    __syncthreads();
    mx = bcastf;

    float s = 0.0f;
    for (int i = tid; i < len; i += SOFT_THREADS) {
        float e = __expf(g_logits[off + i] - mx);
        out[off + i] = e;
        s += e;
    }
    s = wsum(s);
    __syncthreads();
    if (lid == 0) shf[wid] = s;
    __syncthreads();
    if (wid == 0) {
        float v = (lid < nwarp) ? shf[lid] : 0.0f;
        v = wsum(v);
        if (lid == 0) bcastf = v;
    }
    __syncthreads();
    const float inv = 1.0f / bcastf;

    for (int i = tid; i < len; i += SOFT_THREADS) out[off + i] *= inv;
}

__global__ void tail_sizes_kernel(const int* __restrict__ sizes, float* __restrict__ out,
                                  int n, int basepos) {
    int i = blockIdx.x * blockDim.x + threadIdx.x;
    if (i < n) out[basepos + i] = (float)sizes[i];
}

// ---------------------------------------------------------------------------
extern "C" void kernel_launch(void* const* d_in, const int* in_sizes, int n_in,
                              void* d_out, int out_size) {
    const float* x   = (const float*)d_in[0];
    const int* sizes = (const int*)d_in[1];
    const float* W1  = (const float*)d_in[2];
    const float* b1  = (const float*)d_in[3];
    const float* W2  = (const float*)d_in[4];
    const float* b2  = (const float*)d_in[5];
    const float* W3  = (const float*)d_in[6];
    const float* b3  = (const float*)d_in[7];
    const float* W4  = (const float*)d_in[8];
    const float* b4  = (const float*)d_in[9];
    float* out = (float*)d_out;

    const int total  = in_sizes[0] / D_IN;
    const int B      = in_sizes[1];
    const int ntiles = total / TM;

    cudaFuncSetAttribute(mlp_hmma_kernel, cudaFuncAttributeMaxDynamicSharedMemorySize, SMEM_BYTES);

    int blocks = PERSIST_BLOCKS < ntiles ? PERSIST_BLOCKS : ntiles;
    mlp_hmma_kernel<<<blocks, THREADS, SMEM_BYTES>>>(x, ntiles, W1, b1, W2, b2, W3, b3, W4, b4);
    softmax_seg_kernel<<<B, SOFT_THREADS>>>(sizes, out);

    if (out_size > total) {
        int n = out_size - total;
        tail_sizes_kernel<<<(n + 255) / 256, 256>>>(sizes, out, n, total);
    }
}

// round 10
// speedup vs baseline: 7.4002x; 1.0068x over previous
#include <cuda_runtime.h>
#include <cuda_fp16.h>
#include <stdint.h>

#define THREADS 256
#define TM 256               // tokens per CTA iteration (8 warps x 32 tokens)
#define D_IN 64
#define PERSIST_BLOCKS 148   // 1 CTA per SM

// ---- smem byte offsets: LDSM-tiled weights (8n x 8k fp16 tiles, 16B rows) ----
#define W1_B  0          // 32 blocks x 512B = 16384
#define W2_B  16384      // 32 blocks x 512B = 16384
#define W3_B  32768      // 4 blocks x 512B = 2048
#define B1_B  34816      // half2-packed biases: 64 x u32 = 256B
#define B2_B  35072      // 32 x u32 = 128B
#define B3_B  35200      // f32[16]
#define W4_B  35264      // f32[16]
#define SMEM_BYTES 35328

__device__ float g_logits[1 << 20];

// ---- helpers ----
__device__ __forceinline__ uint32_t smem_u32(const void* p) {
    uint32_t a;
    asm("{ .reg .u64 t; cvta.to.shared.u64 t, %1; cvt.u32.u64 %0, t; }" : "=r"(a) : "l"(p));
    return a;
}
__device__ __forceinline__ void mma16816(float* c, const uint32_t* a, uint32_t b0, uint32_t b1) {
    asm volatile(
        "mma.sync.aligned.m16n8k16.row.col.f32.f16.f16.f32 "
        "{%0,%1,%2,%3}, {%4,%5,%6,%7}, {%8,%9}, {%0,%1,%2,%3};"
        : "+f"(c[0]), "+f"(c[1]), "+f"(c[2]), "+f"(c[3])
        : "r"(a[0]), "r"(a[1]), "r"(a[2]), "r"(a[3]), "r"(b0), "r"(b1));
}
__device__ __forceinline__ void ldsm4(uint32_t* d, uint32_t addr) {
    asm volatile("ldmatrix.sync.aligned.m8n8.x4.shared.b16 {%0,%1,%2,%3}, [%4];"
        : "=r"(d[0]), "=r"(d[1]), "=r"(d[2]), "=r"(d[3]) : "r"(addr));
}
__device__ __forceinline__ void prefetchL2(const void* p) {
    asm volatile("prefetch.global.L2 [%0];" :: "l"(p));
}
__device__ __forceinline__ uint32_t packh2(float a, float b) {
    __half2 h = __floats2half2_rn(a, b);
    return *(uint32_t*)&h;
}
// pack two f32 into fp16x2 (lo = first arg)
__device__ __forceinline__ uint32_t pkf2(float lo, float hi) {
    uint32_t r;
    asm("cvt.rn.f16x2.f32 %0, %1, %2;" : "=r"(r) : "f"(hi), "f"(lo));
    return r;
}
// epilogue: tanh(acc + bias) entirely in fp16x2, output = A-fragment word
__device__ __forceinline__ uint32_t tanh2_b(float c0, float c1, uint32_t bias2) {
    uint32_t p = pkf2(c0, c1);
    uint32_t s;
    asm("add.rn.f16x2 %0, %1, %2;" : "=r"(s) : "r"(p), "r"(bias2));
    uint32_t r;
    asm("tanh.approx.f16x2 %0, %1;" : "=r"(r) : "r"(s));
    return r;
}
// f32 tanh for final layer (MUFU.TANH)
__device__ __forceinline__ float tanh_b(float acc, float b) {
    float s = acc + b;
    float r; asm("tanh.approx.f32 %0, %1;" : "=f"(r) : "f"(s));
    return r;
}

// ---------------------------------------------------------------------------
// Persistent fused MLP: 32 tokens per warp per iteration (2 m16 tiles), so
// each ldmatrix.x4 feeds 4 MMAs (weight-read amortization: L1 traffic per
// token halves). fp16x2 epilogue (pack+hadd2+tanh.f16x2). No loop barriers.
// ---------------------------------------------------------------------------
__global__ void __launch_bounds__(THREADS, 1)
mlp_hmma_kernel(const float* __restrict__ x, int ntiles,
                const float* __restrict__ W1, const float* __restrict__ b1,
                const float* __restrict__ W2, const float* __restrict__ b2,
                const float* __restrict__ W3, const float* __restrict__ b3,
                const float* __restrict__ W4, const float* __restrict__ b4) {
    extern __shared__ char smem[];
    uint32_t* sB1 = (uint32_t*)(smem + B1_B);   // half2-packed
    uint32_t* sB2 = (uint32_t*)(smem + B2_B);   // half2-packed
    float* sB3 = (float*)(smem + B3_B);
    float* sW4 = (float*)(smem + W4_B);

    const int tid = threadIdx.x;

    // ---- stage weights once into LDSM tile layout (single fp16) ----
#pragma unroll
    for (int it = 0; it < 32; it++) {             // W1: [64k x 128n]
        int i = tid + it * THREADS;
        int k = i >> 7, n = i & 127;
        __half h = __float2half_rn(W1[i]);
        int kk = k >> 4, khalf = (k >> 3) & 1, kin = k & 7;
        int jp = n >> 4, j01 = (n >> 3) & 1, nin = n & 7;
        uint32_t off = ((((jp << 2) + kk) * 4 + j01 * 2 + khalf) << 7) + (nin << 4) + (kin << 1);
        *(__half*)(smem + W1_B + off) = h;
    }
#pragma unroll
    for (int it = 0; it < 32; it++) {             // W2: [128k x 64n]
        int i = tid + it * THREADS;
        int k = i >> 6, n = i & 63;
        __half h = __float2half_rn(W2[i]);
        int kk = k >> 4, khalf = (k >> 3) & 1, kin = k & 7;
        int jp = n >> 4, j01 = (n >> 3) & 1, nin = n & 7;
        uint32_t off = ((((jp << 3) + kk) * 4 + j01 * 2 + khalf) << 7) + (nin << 4) + (kin << 1);
        *(__half*)(smem + W2_B + off) = h;
    }
#pragma unroll
    for (int it = 0; it < 4; it++) {              // W3: [64k x 16n]
        int i = tid + it * THREADS;
        int k = i >> 4, n = i & 15;
        __half h = __float2half_rn(W3[i]);
        int kk = k >> 4, khalf = (k >> 3) & 1, kin = k & 7;
        int j01 = (n >> 3) & 1, nin = n & 7;
        uint32_t off = (((kk << 2) + j01 * 2 + khalf) << 7) + (nin << 4) + (kin << 1);
        *(__half*)(smem + W3_B + off) = h;
    }
    if (tid < 64) sB1[tid] = packh2(b1[2 * tid], b1[2 * tid + 1]);
    if (tid < 32) sB2[tid] = packh2(b2[2 * tid], b2[2 * tid + 1]);
    if (tid < 16) { sB3[tid] = b3[tid]; sW4[tid] = W4[tid]; }
    __syncthreads();

    const int wid = tid >> 5, lid = tid & 31;
    const int m0 = wid * 32;        // 32 tokens per warp
    const int g  = lid >> 2;        // group row 0..7
    const int q  = lid & 3;         // quad col 0..3
    const float bb4 = b4[0];

    const uint32_t smb = smem_u32(smem);
    const uint32_t lane16 = (uint32_t)lid << 4;
    const uint32_t w1 = smb + W1_B + lane16;
    const uint32_t w2 = smb + W2_B + lane16;
    const uint32_t w3 = smb + W3_B + lane16;

    // -------- persistent tile loop --------
    for (int tile = blockIdx.x; tile < ntiles; tile += gridDim.x) {
        const long long base = (long long)tile * TM;
        const float* xw = x + (base + m0) * D_IN;

        // ---- A1 fragments straight from gmem (fp16), 2 m16 tiles ----
        uint32_t a1[2][4][4];
#pragma unroll
        for (int t = 0; t < 2; t++) {
            const float* xt = xw + t * 16 * D_IN;
#pragma unroll
            for (int kk = 0; kk < 4; kk++) {
                int c0 = q * 2 + 16 * kk;
                float2 p00 = *(const float2*)&xt[g * D_IN + c0];
                float2 p10 = *(const float2*)&xt[(g + 8) * D_IN + c0];
                float2 p01 = *(const float2*)&xt[g * D_IN + c0 + 8];
                float2 p11 = *(const float2*)&xt[(g + 8) * D_IN + c0 + 8];
                a1[t][kk][0] = packh2(p00.x, p00.y);
                a1[t][kk][1] = packh2(p10.x, p10.y);
                a1[t][kk][2] = packh2(p01.x, p01.y);
                a1[t][kk][3] = packh2(p11.x, p11.y);
            }
        }

        // ---- prefetch next tile's X rows into L2 ----
        {
            int nt = tile + gridDim.x;
            if (nt < ntiles) {
                const float* nx = x + ((long long)nt * TM + m0) * D_IN;
                prefetchL2(&nx[g * D_IN + q * 16]);
                prefetchL2(&nx[(g + 8) * D_IN + q * 16]);
                prefetchL2(&nx[(g + 16) * D_IN + q * 16]);
                prefetchL2(&nx[(g + 24) * D_IN + q * 16]);
            }
        }

        // ======== Layer 1: [32x64] @ [64x128] ========
        uint32_t a2[2][8][4];
#pragma unroll
        for (int jp = 0; jp < 8; jp++) {
            float acc[2][8];
#pragma unroll
            for (int t = 0; t < 2; t++)
#pragma unroll
                for (int i = 0; i < 8; i++) acc[t][i] = 0.f;
#pragma unroll
            for (int kk = 0; kk < 4; kk++) {
                uint32_t bh[4];
                ldsm4(bh, w1 + (uint32_t)(jp * 2048 + kk * 512));
                mma16816(&acc[0][0], a1[0][kk], bh[0], bh[1]);
                mma16816(&acc[0][4], a1[0][kk], bh[2], bh[3]);
                mma16816(&acc[1][0], a1[1][kk], bh[0], bh[1]);
                mma16816(&acc[1][4], a1[1][kk], bh[2], bh[3]);
            }
            uint32_t bA = sB1[8 * jp + q];
            uint32_t bB = sB1[8 * jp + 4 + q];
#pragma unroll
            for (int t = 0; t < 2; t++) {
                a2[t][jp][0] = tanh2_b(acc[t][0], acc[t][1], bA);
                a2[t][jp][1] = tanh2_b(acc[t][2], acc[t][3], bA);
                a2[t][jp][2] = tanh2_b(acc[t][4], acc[t][5], bB);
                a2[t][jp][3] = tanh2_b(acc[t][6], acc[t][7], bB);
            }
        }

        // ======== Layer 2: [32x128] @ [128x64] ========
        uint32_t a3[2][4][4];
#pragma unroll
        for (int jp = 0; jp < 4; jp++) {
            float acc[2][8];
#pragma unroll
            for (int t = 0; t < 2; t++)
#pragma unroll
                for (int i = 0; i < 8; i++) acc[t][i] = 0.f;
#pragma unroll
            for (int kk = 0; kk < 8; kk++) {
                uint32_t bh[4];
                ldsm4(bh, w2 + (uint32_t)(jp * 4096 + kk * 512));
                mma16816(&acc[0][0], a2[0][kk], bh[0], bh[1]);
                mma16816(&acc[0][4], a2[0][kk], bh[2], bh[3]);
                mma16816(&acc[1][0], a2[1][kk], bh[0], bh[1]);
                mma16816(&acc[1][4], a2[1][kk], bh[2], bh[3]);
            }
            uint32_t bA = sB2[8 * jp + q];
            uint32_t bB = sB2[8 * jp + 4 + q];
#pragma unroll
            for (int t = 0; t < 2; t++) {
                a3[t][jp][0] = tanh2_b(acc[t][0], acc[t][1], bA);
                a3[t][jp][1] = tanh2_b(acc[t][2], acc[t][3], bA);
                a3[t][jp][2] = tanh2_b(acc[t][4], acc[t][5], bB);
                a3[t][jp][3] = tanh2_b(acc[t][6], acc[t][7], bB);
            }
        }

        // ======== Layer 3: [32x64] @ [64x16] ========
        float acc3[2][8];
#pragma unroll
        for (int t = 0; t < 2; t++)
#pragma unroll
            for (int i = 0; i < 8; i++) acc3[t][i] = 0.f;
#pragma unroll
        for (int kk = 0; kk < 4; kk++) {
            uint32_t bh[4];
            ldsm4(bh, w3 + (uint32_t)(kk * 512));
            mma16816(&acc3[0][0], a3[0][kk], bh[0], bh[1]);
            mma16816(&acc3[0][4], a3[0][kk], bh[2], bh[3]);
            mma16816(&acc3[1][0], a3[1][kk], bh[0], bh[1]);
            mma16816(&acc3[1][4], a3[1][kk], bh[2], bh[3]);
        }

        // ======== epilogue 3 + Layer 4 dot + logits (f32 path) ========
        float2 bpA = *(float2*)&sB3[2 * q];
        float2 bpB = *(float2*)&sB3[8 + 2 * q];
        float2 wpA = *(float2*)&sW4[2 * q];
        float2 wpB = *(float2*)&sW4[8 + 2 * q];
#pragma unroll
        for (int t = 0; t < 2; t++) {
            float s0 = 0.0f, s1 = 0.0f;
            s0 = fmaf(tanh_b(acc3[t][0], bpA.x), wpA.x, s0);
            s0 = fmaf(tanh_b(acc3[t][1], bpA.y), wpA.y, s0);
            s1 = fmaf(tanh_b(acc3[t][2], bpA.x), wpA.x, s1);
            s1 = fmaf(tanh_b(acc3[t][3], bpA.y), wpA.y, s1);
            s0 = fmaf(tanh_b(acc3[t][4], bpB.x), wpB.x, s0);
            s0 = fmaf(tanh_b(acc3[t][5], bpB.y), wpB.y, s0);
            s1 = fmaf(tanh_b(acc3[t][6], bpB.x), wpB.x, s1);
            s1 = fmaf(tanh_b(acc3[t][7], bpB.y), wpB.y, s1);
            s0 += __shfl_xor_sync(0xffffffffu, s0, 1);
            s0 += __shfl_xor_sync(0xffffffffu, s0, 2);
            s1 += __shfl_xor_sync(0xffffffffu, s1, 1);
            s1 += __shfl_xor_sync(0xffffffffu, s1, 2);
            if (q == 0) {
                g_logits[base + m0 + 16 * t + g]     = s0 + bb4;
                g_logits[base + m0 + 16 * t + g + 8] = s1 + bb4;
            }
        }
    }
}

// ---------------------------------------------------------------------------
// Per-segment softmax (global-max subtraction cancels mathematically).
// ---------------------------------------------------------------------------
#define SOFT_THREADS 512

__device__ __forceinline__ float wmax(float v) {
#pragma unroll
    for (int o = 16; o > 0; o >>= 1) v = fmaxf(v, __shfl_xor_sync(0xffffffffu, v, o));
    return v;
}
__device__ __forceinline__ float wsum(float v) {
#pragma unroll
    for (int o = 16; o > 0; o >>= 1) v += __shfl_xor_sync(0xffffffffu, v, o);
    return v;
}
__device__ __forceinline__ int wsumi(int v) {
#pragma unroll
    for (int o = 16; o > 0; o >>= 1) v += __shfl_xor_sync(0xffffffffu, v, o);
    return v;
}

__global__ void __launch_bounds__(SOFT_THREADS)
softmax_seg_kernel(const int* __restrict__ sizes, float* __restrict__ out) {
    __shared__ float shf[16];
    __shared__ int shi[16];
    __shared__ float bcastf;
    __shared__ int bcasti;

    const int b = blockIdx.x, tid = threadIdx.x;
    const int wid = tid >> 5, lid = tid & 31;
    const int nwarp = SOFT_THREADS / 32;

    int part = 0;
    for (int i = tid; i < b; i += SOFT_THREADS) part += sizes[i];
    part = wsumi(part);
    if (lid == 0) shi[wid] = part;
    __syncthreads();
    if (wid == 0) {
        int v = (lid < nwarp) ? shi[lid] : 0;
        v = wsumi(v);
        if (lid == 0) bcasti = v;
    }
    __syncthreads();
    const int off = bcasti;
    const int len = sizes[b];

    float mx = -3.402823466e38f;
    for (int i = tid; i < len; i += SOFT_THREADS) mx = fmaxf(mx, g_logits[off + i]);
    mx = wmax(mx);
    if (lid == 0) shf[wid] = mx;
    __syncthreads();
    if (wid == 0) {
        float v = (lid < nwarp) ? shf[lid] : -3.402823466e38f;
        v = wmax(v);
        if (lid == 0) bcastf = v;
    }
    __syncthreads();
    mx = bcastf;

    float s = 0.0f;
    for (int i = tid; i < len; i += SOFT_THREADS) {
        float e = __expf(g_logits[off + i] - mx);
        out[off + i] = e;
        s += e;
    }
    s = wsum(s);
    __syncthreads();
    if (lid == 0) shf[wid] = s;
    __syncthreads();
    if (wid == 0) {
        float v = (lid < nwarp) ? shf[lid] : 0.0f;
        v = wsum(v);
        if (lid == 0) bcastf = v;
    }
    __syncthreads();
    const float inv = 1.0f / bcastf;

    for (int i = tid; i < len; i += SOFT_THREADS) out[off + i] *= inv;
}

__global__ void tail_sizes_kernel(const int* __restrict__ sizes, float* __restrict__ out,
                                  int n, int basepos) {
    int i = blockIdx.x * blockDim.x + threadIdx.x;
    if (i < n) out[basepos + i] = (float)sizes[i];
}

// ---------------------------------------------------------------------------
extern "C" void kernel_launch(void* const* d_in, const int* in_sizes, int n_in,
                              void* d_out, int out_size) {
    const float* x   = (const float*)d_in[0];
    const int* sizes = (const int*)d_in[1];
    const float* W1  = (const float*)d_in[2];
    const float* b1  = (const float*)d_in[3];
    const float* W2  = (const float*)d_in[4];
    const float* b2  = (const float*)d_in[5];
    const float* W3  = (const float*)d_in[6];
    const float* b3  = (const float*)d_in[7];
    const float* W4  = (const float*)d_in[8];
    const float* b4  = (const float*)d_in[9];
    float* out = (float*)d_out;

    const int total  = in_sizes[0] / D_IN;
    const int B      = in_sizes[1];
    const int ntiles = total / TM;

    cudaFuncSetAttribute(mlp_hmma_kernel, cudaFuncAttributeMaxDynamicSharedMemorySize, SMEM_BYTES);

    int blocks = PERSIST_BLOCKS < ntiles ? PERSIST_BLOCKS : ntiles;
    mlp_hmma_kernel<<<blocks, THREADS, SMEM_BYTES>>>(x, ntiles, W1, b1, W2, b2, W3, b3, W4, b4);
    softmax_seg_kernel<<<B, SOFT_THREADS>>>(sizes, out);

    if (out_size > total) {
        int n = out_size - total;
        tail_sizes_kernel<<<(n + 255) / 256, 256>>>(sizes, out, n, total);
    }
}